// round 1
// baseline (speedup 1.0000x reference)
#include <cuda_runtime.h>
#include <cuda_bf16.h>
#include <math.h>

#define BB 8
#define SS 512
#define DD 768
#define HH 12
#define DH 64
#define LL 12
#define FFD 3072
#define MTOK (BB*SS)   // 4096

// ---------------- scratch (device globals; no allocations allowed) ----------
__device__ float g_h  [MTOK*DD];
__device__ float g_q  [MTOK*DD];
__device__ float g_k  [MTOK*DD];
__device__ float g_v  [MTOK*DD];
__device__ float g_ctx[MTOK*DD];
__device__ float g_t1 [MTOK*DD];
__device__ float g_ff [MTOK*FFD];

// ---------------- helpers ----------------------------------------------------
__device__ __forceinline__ float blockReduceSum(float v, float* red) {
    int lane = threadIdx.x & 31, w = threadIdx.x >> 5;
    #pragma unroll
    for (int o = 16; o; o >>= 1) v += __shfl_xor_sync(0xffffffffu, v, o);
    if (lane == 0) red[w] = v;
    __syncthreads();
    float t = (threadIdx.x < (blockDim.x >> 5)) ? red[threadIdx.x] : 0.f;
    if (w == 0) {
        #pragma unroll
        for (int o = 16; o; o >>= 1) t += __shfl_xor_sync(0xffffffffu, t, o);
        if (lane == 0) red[0] = t;
    }
    __syncthreads();
    return red[0];
}

// ---------------- embedding + layernorm --------------------------------------
__global__ void embed_ln_kernel(const int* __restrict__ ids,
                                const float* __restrict__ we,
                                const float* __restrict__ pe,
                                const float* __restrict__ te,
                                const float* __restrict__ gam,
                                const float* __restrict__ bet,
                                float* __restrict__ out)
{
    __shared__ float xs[DD];
    __shared__ float red[32];
    int tok = blockIdx.x;
    int s   = tok & (SS - 1);
    int id  = ids[tok];
    const float* wrow = we + (size_t)id * DD;
    const float* prow = pe + (size_t)s  * DD;
    int tid = threadIdx.x;

    float sum = 0.f;
    for (int d = tid; d < DD; d += 256) {
        float v = wrow[d] + prow[d] + te[d];
        xs[d] = v; sum += v;
    }
    float mu = blockReduceSum(sum, red) * (1.0f / DD);
    float vs = 0.f;
    for (int d = tid; d < DD; d += 256) { float dl = xs[d] - mu; vs += dl * dl; }
    float var = blockReduceSum(vs, red) * (1.0f / DD);
    float r = rsqrtf(var + 1e-12f);
    float* orow = out + (size_t)tok * DD;
    for (int d = tid; d < DD; d += 256)
        orow[d] = (xs[d] - mu) * r * gam[d] + bet[d];
}

// ---------------- layernorm ---------------------------------------------------
__global__ void layernorm_kernel(const float* __restrict__ x,
                                 const float* __restrict__ gam,
                                 const float* __restrict__ bet,
                                 float* __restrict__ out)
{
    __shared__ float xs[DD];
    __shared__ float red[32];
    int row = blockIdx.x;
    const float* xr = x + (size_t)row * DD;
    int tid = threadIdx.x;
    float sum = 0.f;
    for (int d = tid; d < DD; d += 256) { float v = xr[d]; xs[d] = v; sum += v; }
    float mu = blockReduceSum(sum, red) * (1.0f / DD);
    float vs = 0.f;
    for (int d = tid; d < DD; d += 256) { float dl = xs[d] - mu; vs += dl * dl; }
    float var = blockReduceSum(vs, red) * (1.0f / DD);
    float r = rsqrtf(var + 1e-12f);
    float* orow = out + (size_t)row * DD;
    for (int d = tid; d < DD; d += 256)
        orow[d] = (xs[d] - mu) * r * gam[d] + bet[d];
}

// ---------------- SGEMM: C = A[M,K] @ B[K,N] + bias (+res) (+gelu) ------------
// mode 0: +bias ; mode 1: +bias then exact GELU ; mode 2: +bias +res
#define TM 128
#define TN 128
#define TK 8

__global__ __launch_bounds__(256)
void gemm_kernel(const float* __restrict__ A, const float* __restrict__ B,
                 const float* __restrict__ bias, const float* __restrict__ res,
                 float* __restrict__ C, int M, int N, int K, int mode)
{
    __shared__ float As[TK][TM];
    __shared__ float Bs[TK][TN];

    int tid = threadIdx.x;
    int tx = tid & 15, ty = tid >> 4;
    int mBase = blockIdx.y * TM;
    int nBase = blockIdx.x * TN;

    float acc[8][8];
    #pragma unroll
    for (int i = 0; i < 8; i++)
        #pragma unroll
        for (int j = 0; j < 8; j++) acc[i][j] = 0.f;

    int aRow = tid >> 1;            // 0..127
    int aCol = (tid & 1) * 4;       // 0 or 4
    int bRow = tid >> 5;            // 0..7
    int bCol = (tid & 31) * 4;      // 0..124

    const float* Aptr = A + (size_t)(mBase + aRow) * K + aCol;
    const float* Bptr = B + (size_t)bRow * N + nBase + bCol;

    for (int k0 = 0; k0 < K; k0 += TK) {
        float4 av = *reinterpret_cast<const float4*>(Aptr + k0);
        As[aCol + 0][aRow] = av.x;
        As[aCol + 1][aRow] = av.y;
        As[aCol + 2][aRow] = av.z;
        As[aCol + 3][aRow] = av.w;
        float4 bv = *reinterpret_cast<const float4*>(Bptr + (size_t)k0 * N);
        *reinterpret_cast<float4*>(&Bs[bRow][bCol]) = bv;
        __syncthreads();
        #pragma unroll
        for (int kk = 0; kk < TK; kk++) {
            float4 a0 = *reinterpret_cast<const float4*>(&As[kk][ty * 4]);
            float4 a1 = *reinterpret_cast<const float4*>(&As[kk][64 + ty * 4]);
            float4 b0 = *reinterpret_cast<const float4*>(&Bs[kk][tx * 4]);
            float4 b1 = *reinterpret_cast<const float4*>(&Bs[kk][64 + tx * 4]);
            float a[8] = {a0.x, a0.y, a0.z, a0.w, a1.x, a1.y, a1.z, a1.w};
            float b[8] = {b0.x, b0.y, b0.z, b0.w, b1.x, b1.y, b1.z, b1.w};
            #pragma unroll
            for (int i = 0; i < 8; i++)
                #pragma unroll
                for (int j = 0; j < 8; j++)
                    acc[i][j] += a[i] * b[j];
        }
        __syncthreads();
    }

    #pragma unroll
    for (int i = 0; i < 8; i++) {
        int m = mBase + ((i < 4) ? (ty * 4 + i) : (64 + ty * 4 + (i - 4)));
        const float* rrow = res ? (res + (size_t)m * N) : nullptr;
        float* crow = C + (size_t)m * N;
        #pragma unroll
        for (int j = 0; j < 8; j++) {
            int n = nBase + ((j < 4) ? (tx * 4 + j) : (64 + tx * 4 + (j - 4)));
            float vv = acc[i][j] + bias[n];
            if (mode == 2) vv += rrow[n];
            if (mode == 1) vv = 0.5f * vv * (1.0f + erff(vv * 0.70710678118654752f));
            crow[n] = vv;
        }
    }
}

// ---------------- attention ---------------------------------------------------
// grid: (qt=32, h=12, b=8); block 256 threads; 16 queries per block
__global__ __launch_bounds__(256)
void attn_kernel(const float* __restrict__ q, const float* __restrict__ k,
                 const float* __restrict__ v, const int* __restrict__ mask,
                 float* __restrict__ ctx)
{
    __shared__ float Qs[16][64];
    __shared__ float Ks[32][66];   // pad 66 -> conflict-free stride
    __shared__ float Sc[16][SS];

    int b = blockIdx.z, h = blockIdx.y, qt = blockIdx.x;
    int tid = threadIdx.x;

    const float* qb = q + ((size_t)(b * SS + qt * 16)) * DD + h * DH;
    for (int i = tid; i < 16 * 64; i += 256) {
        int r = i >> 6, d = i & 63;
        Qs[r][d] = qb[(size_t)r * DD + d];
    }

    // scores
    int qr = tid >> 4, tl = tid & 15;
    for (int t0 = 0; t0 < SS; t0 += 32) {
        const float* kb = k + ((size_t)(b * SS + t0)) * DD + h * DH;
        for (int i = tid; i < 32 * 64; i += 256) {
            int r = i >> 6, d = i & 63;
            Ks[r][d] = kb[(size_t)r * DD + d];
        }
        __syncthreads();
        #pragma unroll
        for (int half = 0; half < 2; half++) {
            int tt = tl + half * 16;
            float acc = 0.f;
            #pragma unroll
            for (int d = 0; d < 64; d++) acc += Qs[qr][d] * Ks[tt][d];
            Sc[qr][t0 + tt] = acc * 0.125f;   // 1/sqrt(64)
        }
        __syncthreads();
    }

    // softmax with mask-renormalization (matches reference exactly)
    int warp = tid >> 5, lane = tid & 31;
    const int* mb = mask + b * SS;
    for (int r = warp; r < 16; r += 8) {
        float mx = -1e30f;
        for (int t = lane; t < SS; t += 32) mx = fmaxf(mx, Sc[r][t]);
        #pragma unroll
        for (int o = 16; o; o >>= 1) mx = fmaxf(mx, __shfl_xor_sync(0xffffffffu, mx, o));
        float Z = 0.f, Zm = 0.f;
        for (int t = lane; t < SS; t += 32) {
            float e = __expf(Sc[r][t] - mx);
            float m = (float)mb[t];
            Sc[r][t] = e * m;
            Z += e; Zm += e * m;
        }
        #pragma unroll
        for (int o = 16; o; o >>= 1) {
            Z  += __shfl_xor_sync(0xffffffffu, Z,  o);
            Zm += __shfl_xor_sync(0xffffffffu, Zm, o);
        }
        float denom = fmaxf(Zm / Z, 1e-9f);
        float rcp = 1.0f / (Z * denom);
        for (int t = lane; t < SS; t += 32) Sc[r][t] *= rcp;
    }
    __syncthreads();

    // ctx = probs @ V
    int d = tid & 63, gidx = tid >> 6;   // gidx 0..3 -> 4 query rows each
    float acc[4] = {0.f, 0.f, 0.f, 0.f};
    const float* vb = v + ((size_t)b * SS) * DD + h * DH + d;
    for (int t = 0; t < SS; t++) {
        float vv = vb[(size_t)t * DD];
        #pragma unroll
        for (int i = 0; i < 4; i++) acc[i] += Sc[gidx * 4 + i][t] * vv;
    }
    float* cb = ctx + ((size_t)(b * SS + qt * 16)) * DD + h * DH + d;
    #pragma unroll
    for (int i = 0; i < 4; i++) cb[(size_t)(gidx * 4 + i) * DD] = acc[i];
}

// ---------------- pooling + L2 normalize --------------------------------------
__global__ void pool_kernel(const float* __restrict__ h, const int* __restrict__ mask,
                            float* __restrict__ out)
{
    __shared__ float sent[DD];
    __shared__ float red[32];
    int b = blockIdx.x, tid = threadIdx.x;

    float ms = 0.f;
    for (int s = tid; s < SS; s += 256) ms += (float)mask[b * SS + s];
    ms = blockReduceSum(ms, red);
    float inv = 1.0f / fmaxf(ms, 1e-6f);

    for (int d = tid; d < DD; d += 256) {
        float a = 0.f;
        const float* hp = h + ((size_t)b * SS) * DD + d;
        const int* mp = mask + b * SS;
        for (int s = 0; s < SS; s++) a += hp[(size_t)s * DD] * (float)mp[s];
        sent[d] = a * inv;
    }
    __syncthreads();
    float sq = 0.f;
    for (int d = tid; d < DD; d += 256) sq += sent[d] * sent[d];
    sq = blockReduceSum(sq, red);
    float rn = 1.0f / fmaxf(sqrtf(sq), 1e-12f);
    for (int d = tid; d < DD; d += 256) out[b * DD + d] = sent[d] * rn;
}

// ---------------- launch ------------------------------------------------------
extern "C" void kernel_launch(void* const* d_in, const int* in_sizes, int n_in,
                              void* d_out, int out_size)
{
    const int*   input_ids = (const int*)  d_in[0];
    const int*   amask     = (const int*)  d_in[1];
    const float* word_emb  = (const float*)d_in[2];
    const float* pos_emb   = (const float*)d_in[3];
    const float* type_emb  = (const float*)d_in[4];
    const float* emb_g     = (const float*)d_in[5];
    const float* emb_b     = (const float*)d_in[6];
    const float* Wq = (const float*)d_in[7];  const float* bq = (const float*)d_in[8];
    const float* Wk = (const float*)d_in[9];  const float* bk = (const float*)d_in[10];
    const float* Wv = (const float*)d_in[11]; const float* bv = (const float*)d_in[12];
    const float* Wo = (const float*)d_in[13]; const float* bo = (const float*)d_in[14];
    const float* ln1g = (const float*)d_in[15]; const float* ln1b = (const float*)d_in[16];
    const float* Wi = (const float*)d_in[17]; const float* bi = (const float*)d_in[18];
    const float* Wf = (const float*)d_in[19]; const float* bf = (const float*)d_in[20];
    const float* ln2g = (const float*)d_in[21]; const float* ln2b = (const float*)d_in[22];
    float* out = (float*)d_out;

    float *p_h, *p_q, *p_k, *p_v, *p_ctx, *p_t1, *p_ff;
    cudaGetSymbolAddress((void**)&p_h,   g_h);
    cudaGetSymbolAddress((void**)&p_q,   g_q);
    cudaGetSymbolAddress((void**)&p_k,   g_k);
    cudaGetSymbolAddress((void**)&p_v,   g_v);
    cudaGetSymbolAddress((void**)&p_ctx, g_ctx);
    cudaGetSymbolAddress((void**)&p_t1,  g_t1);
    cudaGetSymbolAddress((void**)&p_ff,  g_ff);

    embed_ln_kernel<<<MTOK, 256>>>(input_ids, word_emb, pos_emb, type_emb,
                                   emb_g, emb_b, p_h);

    dim3 gD (DD  / TN, MTOK / TM);   // (6, 32)
    dim3 gFF(FFD / TN, MTOK / TM);   // (24, 32)

    for (int l = 0; l < LL; l++) {
        const float* wq = Wq + (size_t)l * DD * DD;
        const float* wk = Wk + (size_t)l * DD * DD;
        const float* wv = Wv + (size_t)l * DD * DD;
        const float* wo = Wo + (size_t)l * DD * DD;
        const float* wi = Wi + (size_t)l * DD * FFD;
        const float* wf = Wf + (size_t)l * FFD * DD;

        gemm_kernel<<<gD, 256>>>(p_h, wq, bq + l * DD, nullptr, p_q, MTOK, DD, DD, 0);
        gemm_kernel<<<gD, 256>>>(p_h, wk, bk + l * DD, nullptr, p_k, MTOK, DD, DD, 0);
        gemm_kernel<<<gD, 256>>>(p_h, wv, bv + l * DD, nullptr, p_v, MTOK, DD, DD, 0);

        attn_kernel<<<dim3(SS / 16, HH, BB), 256>>>(p_q, p_k, p_v, amask, p_ctx);

        gemm_kernel<<<gD, 256>>>(p_ctx, wo, bo + l * DD, p_h, p_t1, MTOK, DD, DD, 2);
        layernorm_kernel<<<MTOK, 256>>>(p_t1, ln1g + l * DD, ln1b + l * DD, p_h);

        gemm_kernel<<<gFF, 256>>>(p_h, wi, bi + l * FFD, nullptr, p_ff, MTOK, FFD, DD, 1);
        gemm_kernel<<<gD, 256>>>(p_ff, wf, bf + l * DD, p_h, p_t1, MTOK, DD, FFD, 2);
        layernorm_kernel<<<MTOK, 256>>>(p_t1, ln2g + l * DD, ln2b + l * DD, p_h);
    }

    pool_kernel<<<BB, 256>>>(p_h, amask, out);
}

// round 3
// speedup vs baseline: 1.6112x; 1.6112x over previous
#include <cuda_runtime.h>
#include <cuda_bf16.h>
#include <math.h>
#include <stdint.h>

#define BB 8
#define SS 512
#define DD 768
#define HH 12
#define DH 64
#define LL 12
#define FFD 3072
#define MTOK (BB*SS)   // 4096

// ---------------- scratch (device globals; no allocations allowed) ----------
__device__ __align__(256) float g_h  [MTOK*DD];
__device__ __align__(256) float g_q  [MTOK*DD];
__device__ __align__(256) float g_k  [MTOK*DD];
__device__ __align__(256) float g_v  [MTOK*DD];
__device__ __align__(256) float g_t1 [MTOK*DD];

__device__ __align__(256) __nv_bfloat16 g_h_hi [MTOK*DD];
__device__ __align__(256) __nv_bfloat16 g_h_lo [MTOK*DD];
__device__ __align__(256) __nv_bfloat16 g_ctx_hi[MTOK*DD];
__device__ __align__(256) __nv_bfloat16 g_ctx_lo[MTOK*DD];
__device__ __align__(256) __nv_bfloat16 g_ff_hi[MTOK*FFD];
__device__ __align__(256) __nv_bfloat16 g_ff_lo[MTOK*FFD];

// pre-transposed bf16 hi/lo weights, [N,K] K-major, per layer contiguous
__device__ __align__(256) __nv_bfloat16 g_WqT_h[LL*DD*DD];
__device__ __align__(256) __nv_bfloat16 g_WqT_l[LL*DD*DD];
__device__ __align__(256) __nv_bfloat16 g_WkT_h[LL*DD*DD];
__device__ __align__(256) __nv_bfloat16 g_WkT_l[LL*DD*DD];
__device__ __align__(256) __nv_bfloat16 g_WvT_h[LL*DD*DD];
__device__ __align__(256) __nv_bfloat16 g_WvT_l[LL*DD*DD];
__device__ __align__(256) __nv_bfloat16 g_WoT_h[LL*DD*DD];
__device__ __align__(256) __nv_bfloat16 g_WoT_l[LL*DD*DD];
__device__ __align__(256) __nv_bfloat16 g_WiT_h[LL*DD*FFD];
__device__ __align__(256) __nv_bfloat16 g_WiT_l[LL*DD*FFD];
__device__ __align__(256) __nv_bfloat16 g_WfT_h[LL*DD*FFD];
__device__ __align__(256) __nv_bfloat16 g_WfT_l[LL*DD*FFD];

// ---------------- helpers ------------------------------------------------------
__device__ __forceinline__ uint32_t smem_u32(const void* p) {
    uint32_t a;
    asm("{ .reg .u64 t; cvta.to.shared.u64 t, %1; cvt.u32.u64 %0, t; }" : "=r"(a) : "l"(p));
    return a;
}
__device__ __forceinline__ uint32_t swz(uint32_t o) { return o ^ ((o >> 3) & 0x70); }

__device__ __forceinline__ void cpa16(uint32_t saddr, const void* g) {
    asm volatile("cp.async.cg.shared.global [%0], [%1], 16;" :: "r"(saddr), "l"(g));
}
__device__ __forceinline__ void cp_commit() {
    asm volatile("cp.async.commit_group;" ::: "memory");
}
template <int N>
__device__ __forceinline__ void cp_wait() {
    asm volatile("cp.async.wait_group %0;" :: "n"(N) : "memory");
}
__device__ __forceinline__ void ldsm4(uint32_t& r0, uint32_t& r1, uint32_t& r2, uint32_t& r3,
                                      uint32_t addr) {
    asm volatile("ldmatrix.sync.aligned.m8n8.x4.shared.b16 {%0,%1,%2,%3}, [%4];"
                 : "=r"(r0), "=r"(r1), "=r"(r2), "=r"(r3) : "r"(addr));
}
__device__ __forceinline__ void mma_bf16(float* d, const uint32_t* a, const uint32_t* b) {
    asm volatile("mma.sync.aligned.m16n8k16.row.col.f32.bf16.bf16.f32 "
                 "{%0,%1,%2,%3}, {%4,%5,%6,%7}, {%8,%9}, {%0,%1,%2,%3};"
                 : "+f"(d[0]), "+f"(d[1]), "+f"(d[2]), "+f"(d[3])
                 : "r"(a[0]), "r"(a[1]), "r"(a[2]), "r"(a[3]), "r"(b[0]), "r"(b[1]));
}
__device__ __forceinline__ void split_bf16(float x, __nv_bfloat16& hi, __nv_bfloat16& lo) {
    hi = __float2bfloat16(x);
    lo = __float2bfloat16(x - __bfloat162float(hi));
}

__device__ __forceinline__ float blockReduceSum(float v, float* red) {
    int lane = threadIdx.x & 31, w = threadIdx.x >> 5;
    #pragma unroll
    for (int o = 16; o; o >>= 1) v += __shfl_xor_sync(0xffffffffu, v, o);
    if (lane == 0) red[w] = v;
    __syncthreads();
    float t = (threadIdx.x < (blockDim.x >> 5)) ? red[threadIdx.x] : 0.f;
    if (w == 0) {
        #pragma unroll
        for (int o = 16; o; o >>= 1) t += __shfl_xor_sync(0xffffffffu, t, o);
        if (lane == 0) red[0] = t;
    }
    __syncthreads();
    return red[0];
}

// ---------------- weight transpose + bf16 split -------------------------------
__global__ void transpose_convert(const float* __restrict__ W,
                                  __nv_bfloat16* __restrict__ Th,
                                  __nv_bfloat16* __restrict__ Tl,
                                  int K, int N)
{
    __shared__ float t[32][33];
    size_t base = (size_t)blockIdx.z * K * N;
    const float* src = W + base;
    __nv_bfloat16* th = Th + base;
    __nv_bfloat16* tl = Tl + base;
    int n0 = blockIdx.x * 32, k0 = blockIdx.y * 32;
    for (int i = threadIdx.y; i < 32; i += 8)
        t[i][threadIdx.x] = src[(size_t)(k0 + i) * N + n0 + threadIdx.x];
    __syncthreads();
    for (int i = threadIdx.y; i < 32; i += 8) {
        float v = t[threadIdx.x][i];
        __nv_bfloat16 hi, lo; split_bf16(v, hi, lo);
        size_t o = (size_t)(n0 + i) * K + k0 + threadIdx.x;
        th[o] = hi; tl[o] = lo;
    }
}

// ---------------- embedding + layernorm ---------------------------------------
__global__ void embed_ln_kernel(const int* __restrict__ ids,
                                const float* __restrict__ we,
                                const float* __restrict__ pe,
                                const float* __restrict__ te,
                                const float* __restrict__ gam,
                                const float* __restrict__ bet,
                                float* __restrict__ out,
                                __nv_bfloat16* __restrict__ oh,
                                __nv_bfloat16* __restrict__ ol)
{
    __shared__ float xs[DD];
    __shared__ float red[32];
    int tok = blockIdx.x;
    int s   = tok & (SS - 1);
    int id  = ids[tok];
    const float* wrow = we + (size_t)id * DD;
    const float* prow = pe + (size_t)s  * DD;
    int tid = threadIdx.x;

    float sum = 0.f;
    for (int d = tid; d < DD; d += 256) {
        float v = wrow[d] + prow[d] + te[d];
        xs[d] = v; sum += v;
    }
    float mu = blockReduceSum(sum, red) * (1.0f / DD);
    float vs = 0.f;
    for (int d = tid; d < DD; d += 256) { float dl = xs[d] - mu; vs += dl * dl; }
    float var = blockReduceSum(vs, red) * (1.0f / DD);
    float r = rsqrtf(var + 1e-12f);
    size_t ro = (size_t)tok * DD;
    for (int d = tid; d < DD; d += 256) {
        float o = (xs[d] - mu) * r * gam[d] + bet[d];
        out[ro + d] = o;
        __nv_bfloat16 hi, lo; split_bf16(o, hi, lo);
        oh[ro + d] = hi; ol[ro + d] = lo;
    }
}

__global__ void layernorm_kernel(const float* __restrict__ x,
                                 const float* __restrict__ gam,
                                 const float* __restrict__ bet,
                                 float* __restrict__ out,
                                 __nv_bfloat16* __restrict__ oh,
                                 __nv_bfloat16* __restrict__ ol)
{
    __shared__ float xs[DD];
    __shared__ float red[32];
    int row = blockIdx.x;
    const float* xr = x + (size_t)row * DD;
    int tid = threadIdx.x;
    float sum = 0.f;
    for (int d = tid; d < DD; d += 256) { float v = xr[d]; xs[d] = v; sum += v; }
    float mu = blockReduceSum(sum, red) * (1.0f / DD);
    float vs = 0.f;
    for (int d = tid; d < DD; d += 256) { float dl = xs[d] - mu; vs += dl * dl; }
    float var = blockReduceSum(vs, red) * (1.0f / DD);
    float r = rsqrtf(var + 1e-12f);
    size_t ro = (size_t)row * DD;
    for (int d = tid; d < DD; d += 256) {
        float o = (xs[d] - mu) * r * gam[d] + bet[d];
        out[ro + d] = o;
        __nv_bfloat16 hi, lo; split_bf16(o, hi, lo);
        oh[ro + d] = hi; ol[ro + d] = lo;
    }
}

// ---------------- tensor-core GEMM (mma.sync bf16 split-float) -----------------
// C[M,N] = A[M,K] @ B^T ; A,B bf16 hi/lo; B is [N,K] K-major.
// mode 0: +bias -> C fp32 ; mode 1: +bias,GELU -> Ch/Cl ; mode 2: +bias+res -> C
#define GEMM_SMEM (65536 + 1024)

__global__ __launch_bounds__(256)
void gemm_mma(const __nv_bfloat16* __restrict__ Ah, const __nv_bfloat16* __restrict__ Al,
              const __nv_bfloat16* __restrict__ Bh, const __nv_bfloat16* __restrict__ Bl,
              const float* __restrict__ bias, const float* __restrict__ res,
              float* __restrict__ C,
              __nv_bfloat16* __restrict__ Ch, __nv_bfloat16* __restrict__ Cl,
              int M, int N, int K, int mode)
{
    extern __shared__ char dsm[];
    uint32_t raw = smem_u32(dsm);
    uint32_t s0 = (raw + 1023) & ~1023u;

    int tid = threadIdx.x, wid = tid >> 5, lane = tid & 31;
    int wm = wid & 1, wn = wid >> 1;
    long mBase = (long)blockIdx.y * 128;
    long nBase = (long)blockIdx.x * 128;

    float acc[4][4][4];
    #pragma unroll
    for (int i = 0; i < 4; i++)
        #pragma unroll
        for (int j = 0; j < 4; j++)
            #pragma unroll
            for (int q = 0; q < 4; q++) acc[i][j][q] = 0.f;

    // loader constants: thread handles chunks c = tid*2+rep; row=c>>2, kc=c&3
    int lrow = tid >> 1;               // (tid*2)>>2
    int lkc0 = (tid & 1) * 2;          // chunks 2 per thread: kc0, kc0+1

    const int nIt = K / 32;

    // ---- prologue: stage 0
    {
        int k0 = 0;
        uint32_t sb = s0;
        #pragma unroll
        for (int rep = 0; rep < 2; rep++) {
            int kc = lkc0 + rep;
            size_t aoff = (size_t)(mBase + lrow) * K + k0 + kc * 8;
            size_t boff = (size_t)(nBase + lrow) * K + k0 + kc * 8;
            uint32_t sw = swz(lrow * 64 + kc * 16);
            cpa16(sb +         sw, Ah + aoff);
            cpa16(sb + 8192  + sw, Al + aoff);
            cpa16(sb + 16384 + sw, Bh + boff);
            cpa16(sb + 24576 + sw, Bl + boff);
        }
        cp_commit();
    }

    for (int it = 0; it < nIt; ++it) {
        if (it + 1 < nIt) {
            int k0 = (it + 1) * 32;
            uint32_t sb = s0 + ((it + 1) & 1) * 32768;
            #pragma unroll
            for (int rep = 0; rep < 2; rep++) {
                int kc = lkc0 + rep;
                size_t aoff = (size_t)(mBase + lrow) * K + k0 + kc * 8;
                size_t boff = (size_t)(nBase + lrow) * K + k0 + kc * 8;
                uint32_t sw = swz(lrow * 64 + kc * 16);
                cpa16(sb +         sw, Ah + aoff);
                cpa16(sb + 8192  + sw, Al + aoff);
                cpa16(sb + 16384 + sw, Bh + boff);
                cpa16(sb + 24576 + sw, Bl + boff);
            }
            cp_commit();
            cp_wait<1>();
        } else {
            cp_wait<0>();
        }
        __syncthreads();

        uint32_t base = s0 + (it & 1) * 32768;
        #pragma unroll
        for (int ks = 0; ks < 2; ks++) {
            int arow = wm * 64 + (lane & 15);
            int kcol = (ks * 2 + (lane >> 4)) * 16;
            uint32_t a_h[4][4], a_l[4][4];
            #pragma unroll
            for (int mt = 0; mt < 4; mt++) {
                uint32_t ad = base + swz((arow + mt * 16) * 64 + kcol);
                ldsm4(a_h[mt][0], a_h[mt][1], a_h[mt][2], a_h[mt][3], ad);
            }
            int brow = wn * 32 + (lane & 15);
            uint32_t b_h[4][2], b_l[4][2];
            #pragma unroll
            for (int nt2 = 0; nt2 < 2; nt2++) {
                uint32_t r0, r1, r2, r3;
                uint32_t bd = base + 16384 + swz((brow + nt2 * 16) * 64 + kcol);
                ldsm4(r0, r1, r2, r3, bd);
                b_h[nt2*2][0] = r0; b_h[nt2*2][1] = r2;
                b_h[nt2*2+1][0] = r1; b_h[nt2*2+1][1] = r3;
            }
            // hh
            #pragma unroll
            for (int mt = 0; mt < 4; mt++)
                #pragma unroll
                for (int nt = 0; nt < 4; nt++)
                    mma_bf16(acc[mt][nt], a_h[mt], b_h[nt]);
            // lo-A
            #pragma unroll
            for (int mt = 0; mt < 4; mt++) {
                uint32_t ad = base + 8192 + swz((arow + mt * 16) * 64 + kcol);
                ldsm4(a_l[mt][0], a_l[mt][1], a_l[mt][2], a_l[mt][3], ad);
            }
            #pragma unroll
            for (int mt = 0; mt < 4; mt++)
                #pragma unroll
                for (int nt = 0; nt < 4; nt++)
                    mma_bf16(acc[mt][nt], a_l[mt], b_h[nt]);
            // lo-B
            #pragma unroll
            for (int nt2 = 0; nt2 < 2; nt2++) {
                uint32_t r0, r1, r2, r3;
                uint32_t bd = base + 24576 + swz((brow + nt2 * 16) * 64 + kcol);
                ldsm4(r0, r1, r2, r3, bd);
                b_l[nt2*2][0] = r0; b_l[nt2*2][1] = r2;
                b_l[nt2*2+1][0] = r1; b_l[nt2*2+1][1] = r3;
            }
            #pragma unroll
            for (int mt = 0; mt < 4; mt++)
                #pragma unroll
                for (int nt = 0; nt < 4; nt++)
                    mma_bf16(acc[mt][nt], a_h[mt], b_l[nt]);
        }
        __syncthreads();
    }

    // ---- epilogue
    #pragma unroll
    for (int mt = 0; mt < 4; mt++) {
        #pragma unroll
        for (int half = 0; half < 2; half++) {
            long m = mBase + wm * 64 + mt * 16 + (lane >> 2) + half * 8;
            #pragma unroll
            for (int nt = 0; nt < 4; nt++) {
                long n0 = nBase + wn * 32 + nt * 8 + (lane & 3) * 2;
                float v0 = acc[mt][nt][half * 2 + 0] + __ldg(bias + n0);
                float v1 = acc[mt][nt][half * 2 + 1] + __ldg(bias + n0 + 1);
                if (mode == 2) {
                    const float2 rv = *(const float2*)(res + m * N + n0);
                    v0 += rv.x; v1 += rv.y;
                }
                if (mode == 1) {
                    v0 = 0.5f * v0 * (1.0f + erff(v0 * 0.70710678118654752f));
                    v1 = 0.5f * v1 * (1.0f + erff(v1 * 0.70710678118654752f));
                }
                if (C) {
                    *(float2*)(C + m * N + n0) = make_float2(v0, v1);
                }
                if (Ch) {
                    __nv_bfloat16 h0, l0, h1, l1;
                    split_bf16(v0, h0, l0);
                    split_bf16(v1, h1, l1);
                    *(__nv_bfloat162*)(Ch + m * N + n0) = __nv_bfloat162(h0, h1);
                    *(__nv_bfloat162*)(Cl + m * N + n0) = __nv_bfloat162(l0, l1);
                }
            }
        }
    }
}

// ---------------- attention ----------------------------------------------------
__global__ __launch_bounds__(256)
void attn_kernel(const float* __restrict__ q, const float* __restrict__ k,
                 const float* __restrict__ v, const int* __restrict__ mask,
                 __nv_bfloat16* __restrict__ ctx_hi, __nv_bfloat16* __restrict__ ctx_lo)
{
    __shared__ float Qs[16][64];
    __shared__ float Ks[32][66];
    __shared__ float Sc[16][SS];

    int b = blockIdx.z, h = blockIdx.y, qt = blockIdx.x;
    int tid = threadIdx.x;

    const float* qb = q + ((size_t)(b * SS + qt * 16)) * DD + h * DH;
    for (int i = tid; i < 16 * 64; i += 256) {
        int r = i >> 6, d = i & 63;
        Qs[r][d] = qb[(size_t)r * DD + d];
    }

    int qr = tid >> 4, tl = tid & 15;
    for (int t0 = 0; t0 < SS; t0 += 32) {
        const float* kb = k + ((size_t)(b * SS + t0)) * DD + h * DH;
        for (int i = tid; i < 32 * 64; i += 256) {
            int r = i >> 6, d = i & 63;
            Ks[r][d] = kb[(size_t)r * DD + d];
        }
        __syncthreads();
        #pragma unroll
        for (int half = 0; half < 2; half++) {
            int tt = tl + half * 16;
            float acc = 0.f;
            #pragma unroll
            for (int d = 0; d < 64; d++) acc += Qs[qr][d] * Ks[tt][d];
            Sc[qr][t0 + tt] = acc * 0.125f;
        }
        __syncthreads();
    }

    int warp = tid >> 5, lane = tid & 31;
    const int* mb = mask + b * SS;
    for (int r = warp; r < 16; r += 8) {
        float mx = -1e30f;
        for (int t = lane; t < SS; t += 32) mx = fmaxf(mx, Sc[r][t]);
        #pragma unroll
        for (int o = 16; o; o >>= 1) mx = fmaxf(mx, __shfl_xor_sync(0xffffffffu, mx, o));
        float Z = 0.f, Zm = 0.f;
        for (int t = lane; t < SS; t += 32) {
            float e = __expf(Sc[r][t] - mx);
            float mm = (float)mb[t];
            Sc[r][t] = e * mm;
            Z += e; Zm += e * mm;
        }
        #pragma unroll
        for (int o = 16; o; o >>= 1) {
            Z  += __shfl_xor_sync(0xffffffffu, Z,  o);
            Zm += __shfl_xor_sync(0xffffffffu, Zm, o);
        }
        float denom = fmaxf(Zm / Z, 1e-9f);
        float rcp = 1.0f / (Z * denom);
        for (int t = lane; t < SS; t += 32) Sc[r][t] *= rcp;
    }
    __syncthreads();

    int d = tid & 63, gidx = tid >> 6;
    float acc[4] = {0.f, 0.f, 0.f, 0.f};
    const float* vb = v + ((size_t)b * SS) * DD + h * DH + d;
    for (int t = 0; t < SS; t++) {
        float vv = vb[(size_t)t * DD];
        #pragma unroll
        for (int i = 0; i < 4; i++) acc[i] += Sc[gidx * 4 + i][t] * vv;
    }
    size_t cb = ((size_t)(b * SS + qt * 16)) * DD + h * DH + d;
    #pragma unroll
    for (int i = 0; i < 4; i++) {
        __nv_bfloat16 hi, lo; split_bf16(acc[i], hi, lo);
        ctx_hi[cb + (size_t)(gidx * 4 + i) * DD] = hi;
        ctx_lo[cb + (size_t)(gidx * 4 + i) * DD] = lo;
    }
}

// ---------------- pooling + L2 normalize ---------------------------------------
__global__ void pool_kernel(const float* __restrict__ h, const int* __restrict__ mask,
                            float* __restrict__ out)
{
    __shared__ float sent[DD];
    __shared__ float red[32];
    int b = blockIdx.x, tid = threadIdx.x;

    float ms = 0.f;
    for (int s = tid; s < SS; s += 256) ms += (float)mask[b * SS + s];
    ms = blockReduceSum(ms, red);
    float inv = 1.0f / fmaxf(ms, 1e-6f);

    for (int d = tid; d < DD; d += 256) {
        float a = 0.f;
        const float* hp = h + ((size_t)b * SS) * DD + d;
        const int* mp = mask + b * SS;
        for (int s = 0; s < SS; s++) a += hp[(size_t)s * DD] * (float)mp[s];
        sent[d] = a * inv;
    }
    __syncthreads();
    float sq = 0.f;
    for (int d = tid; d < DD; d += 256) sq += sent[d] * sent[d];
    sq = blockReduceSum(sq, red);
    float rn = 1.0f / fmaxf(sqrtf(sq), 1e-12f);
    for (int d = tid; d < DD; d += 256) out[b * DD + d] = sent[d] * rn;
}

// ---------------- launch --------------------------------------------------------
extern "C" void kernel_launch(void* const* d_in, const int* in_sizes, int n_in,
                              void* d_out, int out_size)
{
    const int*   input_ids = (const int*)  d_in[0];
    const int*   amask     = (const int*)  d_in[1];
    const float* word_emb  = (const float*)d_in[2];
    const float* pos_emb   = (const float*)d_in[3];
    const float* type_emb  = (const float*)d_in[4];
    const float* emb_g     = (const float*)d_in[5];
    const float* emb_b     = (const float*)d_in[6];
    const float* Wq = (const float*)d_in[7];  const float* bq = (const float*)d_in[8];
    const float* Wk = (const float*)d_in[9];  const float* bk = (const float*)d_in[10];
    const float* Wv = (const float*)d_in[11]; const float* bv = (const float*)d_in[12];
    const float* Wo = (const float*)d_in[13]; const float* bo = (const float*)d_in[14];
    const float* ln1g = (const float*)d_in[15]; const float* ln1b = (const float*)d_in[16];
    const float* Wi = (const float*)d_in[17]; const float* bi = (const float*)d_in[18];
    const float* Wf = (const float*)d_in[19]; const float* bf = (const float*)d_in[20];
    const float* ln2g = (const float*)d_in[21]; const float* ln2b = (const float*)d_in[22];
    float* out = (float*)d_out;

    float *p_h, *p_q, *p_k, *p_v, *p_t1;
    __nv_bfloat16 *p_hh, *p_hl, *p_ch, *p_cl, *p_fh, *p_fl;
    __nv_bfloat16 *wq_h, *wq_l, *wk_h, *wk_l, *wv_h, *wv_l, *wo_h, *wo_l;
    __nv_bfloat16 *wi_h, *wi_l, *wf_h, *wf_l;
    cudaGetSymbolAddress((void**)&p_h,  g_h);
    cudaGetSymbolAddress((void**)&p_q,  g_q);
    cudaGetSymbolAddress((void**)&p_k,  g_k);
    cudaGetSymbolAddress((void**)&p_v,  g_v);
    cudaGetSymbolAddress((void**)&p_t1, g_t1);
    cudaGetSymbolAddress((void**)&p_hh, g_h_hi);
    cudaGetSymbolAddress((void**)&p_hl, g_h_lo);
    cudaGetSymbolAddress((void**)&p_ch, g_ctx_hi);
    cudaGetSymbolAddress((void**)&p_cl, g_ctx_lo);
    cudaGetSymbolAddress((void**)&p_fh, g_ff_hi);
    cudaGetSymbolAddress((void**)&p_fl, g_ff_lo);
    cudaGetSymbolAddress((void**)&wq_h, g_WqT_h); cudaGetSymbolAddress((void**)&wq_l, g_WqT_l);
    cudaGetSymbolAddress((void**)&wk_h, g_WkT_h); cudaGetSymbolAddress((void**)&wk_l, g_WkT_l);
    cudaGetSymbolAddress((void**)&wv_h, g_WvT_h); cudaGetSymbolAddress((void**)&wv_l, g_WvT_l);
    cudaGetSymbolAddress((void**)&wo_h, g_WoT_h); cudaGetSymbolAddress((void**)&wo_l, g_WoT_l);
    cudaGetSymbolAddress((void**)&wi_h, g_WiT_h); cudaGetSymbolAddress((void**)&wi_l, g_WiT_l);
    cudaGetSymbolAddress((void**)&wf_h, g_WfT_h); cudaGetSymbolAddress((void**)&wf_l, g_WfT_l);

    cudaFuncSetAttribute(gemm_mma, cudaFuncAttributeMaxDynamicSharedMemorySize, GEMM_SMEM);

    dim3 tb(32, 8);
    transpose_convert<<<dim3(DD/32,  DD/32,  LL), tb>>>(Wq, wq_h, wq_l, DD, DD);
    transpose_convert<<<dim3(DD/32,  DD/32,  LL), tb>>>(Wk, wk_h, wk_l, DD, DD);
    transpose_convert<<<dim3(DD/32,  DD/32,  LL), tb>>>(Wv, wv_h, wv_l, DD, DD);
    transpose_convert<<<dim3(DD/32,  DD/32,  LL), tb>>>(Wo, wo_h, wo_l, DD, DD);
    transpose_convert<<<dim3(FFD/32, DD/32,  LL), tb>>>(Wi, wi_h, wi_l, DD, FFD);
    transpose_convert<<<dim3(DD/32,  FFD/32, LL), tb>>>(Wf, wf_h, wf_l, FFD, DD);

    embed_ln_kernel<<<MTOK, 256>>>(input_ids, word_emb, pos_emb, type_emb,
                                   emb_g, emb_b, p_h, p_hh, p_hl);

    dim3 gD (DD  / 128, MTOK / 128);   // (6, 32)
    dim3 gFF(FFD / 128, MTOK / 128);   // (24, 32)

    for (int l = 0; l < LL; l++) {
        size_t wdd = (size_t)l * DD * DD;
        size_t wdf = (size_t)l * DD * FFD;

        gemm_mma<<<gD, 256, GEMM_SMEM>>>(p_hh, p_hl, wq_h + wdd, wq_l + wdd,
                                         bq + l * DD, nullptr, p_q, nullptr, nullptr,
                                         MTOK, DD, DD, 0);
        gemm_mma<<<gD, 256, GEMM_SMEM>>>(p_hh, p_hl, wk_h + wdd, wk_l + wdd,
                                         bk + l * DD, nullptr, p_k, nullptr, nullptr,
                                         MTOK, DD, DD, 0);
        gemm_mma<<<gD, 256, GEMM_SMEM>>>(p_hh, p_hl, wv_h + wdd, wv_l + wdd,
                                         bv + l * DD, nullptr, p_v, nullptr, nullptr,
                                         MTOK, DD, DD, 0);

        attn_kernel<<<dim3(SS / 16, HH, BB), 256>>>(p_q, p_k, p_v, amask, p_ch, p_cl);

        gemm_mma<<<gD, 256, GEMM_SMEM>>>(p_ch, p_cl, wo_h + wdd, wo_l + wdd,
                                         bo + l * DD, p_h, p_t1, nullptr, nullptr,
                                         MTOK, DD, DD, 2);
        layernorm_kernel<<<MTOK, 256>>>(p_t1, ln1g + l * DD, ln1b + l * DD,
                                        p_h, p_hh, p_hl);

        gemm_mma<<<gFF, 256, GEMM_SMEM>>>(p_hh, p_hl, wi_h + wdf, wi_l + wdf,
                                          bi + l * FFD, nullptr, nullptr, p_fh, p_fl,
                                          MTOK, FFD, DD, 1);
        gemm_mma<<<gD, 256, GEMM_SMEM>>>(p_fh, p_fl, wf_h + wdf, wf_l + wdf,
                                         bf + l * DD, p_h, p_t1, nullptr, nullptr,
                                         MTOK, DD, FFD, 2);
        layernorm_kernel<<<MTOK, 256>>>(p_t1, ln2g + l * DD, ln2b + l * DD,
                                        p_h, p_hh, p_hl);
    }

    pool_kernel<<<BB, 256>>>(p_h, amask, out);
}

// round 4
// speedup vs baseline: 1.6165x; 1.0033x over previous
#include <cuda_runtime.h>
#include <cuda_bf16.h>
#include <math.h>
#include <stdint.h>

#define BB 8
#define SS 512
#define DD 768
#define HH 12
#define DH 64
#define LL 12
#define FFD 3072
#define MTOK (BB*SS)   // 4096

// ---------------- scratch (device globals; no allocations allowed) ----------
__device__ __align__(256) float g_h  [MTOK*DD];
__device__ __align__(256) float g_q  [MTOK*DD];
__device__ __align__(256) float g_k  [MTOK*DD];
__device__ __align__(256) float g_v  [MTOK*DD];
__device__ __align__(256) float g_t1 [MTOK*DD];

__device__ __align__(256) __nv_bfloat16 g_h_hi [MTOK*DD];
__device__ __align__(256) __nv_bfloat16 g_h_lo [MTOK*DD];
__device__ __align__(256) __nv_bfloat16 g_ctx_hi[MTOK*DD];
__device__ __align__(256) __nv_bfloat16 g_ctx_lo[MTOK*DD];
__device__ __align__(256) __nv_bfloat16 g_ff_hi[MTOK*FFD];
__device__ __align__(256) __nv_bfloat16 g_ff_lo[MTOK*FFD];

// pre-transposed bf16 hi/lo weights, [N,K] K-major, per layer contiguous
__device__ __align__(256) __nv_bfloat16 g_WqT_h[LL*DD*DD];
__device__ __align__(256) __nv_bfloat16 g_WqT_l[LL*DD*DD];
__device__ __align__(256) __nv_bfloat16 g_WkT_h[LL*DD*DD];
__device__ __align__(256) __nv_bfloat16 g_WkT_l[LL*DD*DD];
__device__ __align__(256) __nv_bfloat16 g_WvT_h[LL*DD*DD];
__device__ __align__(256) __nv_bfloat16 g_WvT_l[LL*DD*DD];
__device__ __align__(256) __nv_bfloat16 g_WoT_h[LL*DD*DD];
__device__ __align__(256) __nv_bfloat16 g_WoT_l[LL*DD*DD];
__device__ __align__(256) __nv_bfloat16 g_WiT_h[LL*DD*FFD];
__device__ __align__(256) __nv_bfloat16 g_WiT_l[LL*DD*FFD];
__device__ __align__(256) __nv_bfloat16 g_WfT_h[LL*DD*FFD];
__device__ __align__(256) __nv_bfloat16 g_WfT_l[LL*DD*FFD];

// ---------------- helpers ------------------------------------------------------
__device__ __forceinline__ uint32_t smem_u32(const void* p) {
    uint32_t a;
    asm("{ .reg .u64 t; cvta.to.shared.u64 t, %1; cvt.u32.u64 %0, t; }" : "=r"(a) : "l"(p));
    return a;
}
__device__ __forceinline__ uint32_t swz(uint32_t o) { return o ^ ((o >> 3) & 0x70); }

__device__ __forceinline__ void cpa16(uint32_t saddr, const void* g) {
    asm volatile("cp.async.cg.shared.global [%0], [%1], 16;" :: "r"(saddr), "l"(g));
}
__device__ __forceinline__ void cp_commit() {
    asm volatile("cp.async.commit_group;" ::: "memory");
}
template <int N>
__device__ __forceinline__ void cp_wait() {
    asm volatile("cp.async.wait_group %0;" :: "n"(N) : "memory");
}
__device__ __forceinline__ void ldsm4(uint32_t& r0, uint32_t& r1, uint32_t& r2, uint32_t& r3,
                                      uint32_t addr) {
    asm volatile("ldmatrix.sync.aligned.m8n8.x4.shared.b16 {%0,%1,%2,%3}, [%4];"
                 : "=r"(r0), "=r"(r1), "=r"(r2), "=r"(r3) : "r"(addr));
}
__device__ __forceinline__ void mma_bf16(float* d, const uint32_t* a, const uint32_t* b) {
    asm volatile("mma.sync.aligned.m16n8k16.row.col.f32.bf16.bf16.f32 "
                 "{%0,%1,%2,%3}, {%4,%5,%6,%7}, {%8,%9}, {%0,%1,%2,%3};"
                 : "+f"(d[0]), "+f"(d[1]), "+f"(d[2]), "+f"(d[3])
                 : "r"(a[0]), "r"(a[1]), "r"(a[2]), "r"(a[3]), "r"(b[0]), "r"(b[1]));
}
__device__ __forceinline__ void split_bf16(float x, __nv_bfloat16& hi, __nv_bfloat16& lo) {
    hi = __float2bfloat16(x);
    lo = __float2bfloat16(x - __bfloat162float(hi));
}

__device__ __forceinline__ float blockReduceSum(float v, float* red) {
    int lane = threadIdx.x & 31, w = threadIdx.x >> 5;
    #pragma unroll
    for (int o = 16; o; o >>= 1) v += __shfl_xor_sync(0xffffffffu, v, o);
    if (lane == 0) red[w] = v;
    __syncthreads();
    float t = (threadIdx.x < (blockDim.x >> 5)) ? red[threadIdx.x] : 0.f;
    if (w == 0) {
        #pragma unroll
        for (int o = 16; o; o >>= 1) t += __shfl_xor_sync(0xffffffffu, t, o);
        if (lane == 0) red[0] = t;
    }
    __syncthreads();
    return red[0];
}

// ---------------- weight transpose + bf16 split -------------------------------
__global__ void transpose_convert(const float* __restrict__ W,
                                  __nv_bfloat16* __restrict__ Th,
                                  __nv_bfloat16* __restrict__ Tl,
                                  int K, int N)
{
    __shared__ float t[32][33];
    size_t base = (size_t)blockIdx.z * K * N;
    const float* src = W + base;
    __nv_bfloat16* th = Th + base;
    __nv_bfloat16* tl = Tl + base;
    int n0 = blockIdx.x * 32, k0 = blockIdx.y * 32;
    for (int i = threadIdx.y; i < 32; i += 8)
        t[i][threadIdx.x] = src[(size_t)(k0 + i) * N + n0 + threadIdx.x];
    __syncthreads();
    for (int i = threadIdx.y; i < 32; i += 8) {
        float v = t[threadIdx.x][i];
        __nv_bfloat16 hi, lo; split_bf16(v, hi, lo);
        size_t o = (size_t)(n0 + i) * K + k0 + threadIdx.x;
        th[o] = hi; tl[o] = lo;
    }
}

// ---------------- embedding + layernorm ---------------------------------------
__global__ void embed_ln_kernel(const int* __restrict__ ids,
                                const float* __restrict__ we,
                                const float* __restrict__ pe,
                                const float* __restrict__ te,
                                const float* __restrict__ gam,
                                const float* __restrict__ bet,
                                float* __restrict__ out,
                                __nv_bfloat16* __restrict__ oh,
                                __nv_bfloat16* __restrict__ ol)
{
    __shared__ float xs[DD];
    __shared__ float red[32];
    int tok = blockIdx.x;
    int s   = tok & (SS - 1);
    int id  = ids[tok];
    const float* wrow = we + (size_t)id * DD;
    const float* prow = pe + (size_t)s  * DD;
    int tid = threadIdx.x;

    float sum = 0.f;
    for (int d = tid; d < DD; d += 256) {
        float v = wrow[d] + prow[d] + te[d];
        xs[d] = v; sum += v;
    }
    float mu = blockReduceSum(sum, red) * (1.0f / DD);
    float vs = 0.f;
    for (int d = tid; d < DD; d += 256) { float dl = xs[d] - mu; vs += dl * dl; }
    float var = blockReduceSum(vs, red) * (1.0f / DD);
    float r = rsqrtf(var + 1e-12f);
    size_t ro = (size_t)tok * DD;
    for (int d = tid; d < DD; d += 256) {
        float o = (xs[d] - mu) * r * gam[d] + bet[d];
        out[ro + d] = o;
        __nv_bfloat16 hi, lo; split_bf16(o, hi, lo);
        oh[ro + d] = hi; ol[ro + d] = lo;
    }
}

__global__ void layernorm_kernel(const float* __restrict__ x,
                                 const float* __restrict__ gam,
                                 const float* __restrict__ bet,
                                 float* __restrict__ out,
                                 __nv_bfloat16* __restrict__ oh,
                                 __nv_bfloat16* __restrict__ ol)
{
    __shared__ float xs[DD];
    __shared__ float red[32];
    int row = blockIdx.x;
    const float* xr = x + (size_t)row * DD;
    int tid = threadIdx.x;
    float sum = 0.f;
    for (int d = tid; d < DD; d += 256) { float v = xr[d]; xs[d] = v; sum += v; }
    float mu = blockReduceSum(sum, red) * (1.0f / DD);
    float vs = 0.f;
    for (int d = tid; d < DD; d += 256) { float dl = xs[d] - mu; vs += dl * dl; }
    float var = blockReduceSum(vs, red) * (1.0f / DD);
    float r = rsqrtf(var + 1e-12f);
    size_t ro = (size_t)row * DD;
    for (int d = tid; d < DD; d += 256) {
        float o = (xs[d] - mu) * r * gam[d] + bet[d];
        out[ro + d] = o;
        __nv_bfloat16 hi, lo; split_bf16(o, hi, lo);
        oh[ro + d] = hi; ol[ro + d] = lo;
    }
}

// ---------------- tensor-core GEMM (mma.sync bf16 split-float) -----------------
// C[M,N] = A[M,K] @ B^T ; A,B bf16 hi/lo; B is [N,K] K-major.
// mode 0: +bias -> C fp32 ; mode 1: +bias,GELU -> Ch/Cl ; mode 2: +bias+res -> C
#define GEMM_SMEM (65536 + 1024)

__global__ __launch_bounds__(256)
void gemm_mma(const __nv_bfloat16* __restrict__ Ah, const __nv_bfloat16* __restrict__ Al,
              const __nv_bfloat16* __restrict__ Bh, const __nv_bfloat16* __restrict__ Bl,
              const float* __restrict__ bias, const float* __restrict__ res,
              float* __restrict__ C,
              __nv_bfloat16* __restrict__ Ch, __nv_bfloat16* __restrict__ Cl,
              int M, int N, int K, int mode)
{
    extern __shared__ char dsm[];
    uint32_t raw = smem_u32(dsm);
    uint32_t s0 = (raw + 1023) & ~1023u;

    int tid = threadIdx.x, wid = tid >> 5, lane = tid & 31;
    int wm = wid & 1, wn = wid >> 1;
    long mBase = (long)blockIdx.y * 128;
    long nBase = (long)blockIdx.x * 128;

    float acc[4][4][4];
    #pragma unroll
    for (int i = 0; i < 4; i++)
        #pragma unroll
        for (int j = 0; j < 4; j++)
            #pragma unroll
            for (int q = 0; q < 4; q++) acc[i][j][q] = 0.f;

    // loader constants: thread handles chunks c = tid*2+rep; row=c>>2, kc=c&3
    int lrow = tid >> 1;               // (tid*2)>>2
    int lkc0 = (tid & 1) * 2;          // chunks 2 per thread: kc0, kc0+1

    const int nIt = K / 32;

    // ---- prologue: stage 0
    {
        int k0 = 0;
        uint32_t sb = s0;
        #pragma unroll
        for (int rep = 0; rep < 2; rep++) {
            int kc = lkc0 + rep;
            size_t aoff = (size_t)(mBase + lrow) * K + k0 + kc * 8;
            size_t boff = (size_t)(nBase + lrow) * K + k0 + kc * 8;
            uint32_t sw = swz(lrow * 64 + kc * 16);
            cpa16(sb +         sw, Ah + aoff);
            cpa16(sb + 8192  + sw, Al + aoff);
            cpa16(sb + 16384 + sw, Bh + boff);
            cpa16(sb + 24576 + sw, Bl + boff);
        }
        cp_commit();
    }

    for (int it = 0; it < nIt; ++it) {
        if (it + 1 < nIt) {
            int k0 = (it + 1) * 32;
            uint32_t sb = s0 + ((it + 1) & 1) * 32768;
            #pragma unroll
            for (int rep = 0; rep < 2; rep++) {
                int kc = lkc0 + rep;
                size_t aoff = (size_t)(mBase + lrow) * K + k0 + kc * 8;
                size_t boff = (size_t)(nBase + lrow) * K + k0 + kc * 8;
                uint32_t sw = swz(lrow * 64 + kc * 16);
                cpa16(sb +         sw, Ah + aoff);
                cpa16(sb + 8192  + sw, Al + aoff);
                cpa16(sb + 16384 + sw, Bh + boff);
                cpa16(sb + 24576 + sw, Bl + boff);
            }
            cp_commit();
            cp_wait<1>();
        } else {
            cp_wait<0>();
        }
        __syncthreads();

        uint32_t base = s0 + (it & 1) * 32768;
        #pragma unroll
        for (int ks = 0; ks < 2; ks++) {
            int arow = wm * 64 + (lane & 15);
            int kcol = (ks * 2 + (lane >> 4)) * 16;
            uint32_t a_h[4][4], a_l[4][4];
            #pragma unroll
            for (int mt = 0; mt < 4; mt++) {
                uint32_t ad = base + swz((arow + mt * 16) * 64 + kcol);
                ldsm4(a_h[mt][0], a_h[mt][1], a_h[mt][2], a_h[mt][3], ad);
            }
            int brow = wn * 32 + (lane & 15);
            uint32_t b_h[4][2], b_l[4][2];
            #pragma unroll
            for (int nt2 = 0; nt2 < 2; nt2++) {
                uint32_t r0, r1, r2, r3;
                uint32_t bd = base + 16384 + swz((brow + nt2 * 16) * 64 + kcol);
                ldsm4(r0, r1, r2, r3, bd);
                b_h[nt2*2][0] = r0; b_h[nt2*2][1] = r2;
                b_h[nt2*2+1][0] = r1; b_h[nt2*2+1][1] = r3;
            }
            // hh
            #pragma unroll
            for (int mt = 0; mt < 4; mt++)
                #pragma unroll
                for (int nt = 0; nt < 4; nt++)
                    mma_bf16(acc[mt][nt], a_h[mt], b_h[nt]);
            // lo-A
            #pragma unroll
            for (int mt = 0; mt < 4; mt++) {
                uint32_t ad = base + 8192 + swz((arow + mt * 16) * 64 + kcol);
                ldsm4(a_l[mt][0], a_l[mt][1], a_l[mt][2], a_l[mt][3], ad);
            }
            #pragma unroll
            for (int mt = 0; mt < 4; mt++)
                #pragma unroll
                for (int nt = 0; nt < 4; nt++)
                    mma_bf16(acc[mt][nt], a_l[mt], b_h[nt]);
            // lo-B
            #pragma unroll
            for (int nt2 = 0; nt2 < 2; nt2++) {
                uint32_t r0, r1, r2, r3;
                uint32_t bd = base + 24576 + swz((brow + nt2 * 16) * 64 + kcol);
                ldsm4(r0, r1, r2, r3, bd);
                b_l[nt2*2][0] = r0; b_l[nt2*2][1] = r2;
                b_l[nt2*2+1][0] = r1; b_l[nt2*2+1][1] = r3;
            }
            #pragma unroll
            for (int mt = 0; mt < 4; mt++)
                #pragma unroll
                for (int nt = 0; nt < 4; nt++)
                    mma_bf16(acc[mt][nt], a_h[mt], b_l[nt]);
        }
        __syncthreads();
    }

    // ---- epilogue
    #pragma unroll
    for (int mt = 0; mt < 4; mt++) {
        #pragma unroll
        for (int half = 0; half < 2; half++) {
            long m = mBase + wm * 64 + mt * 16 + (lane >> 2) + half * 8;
            #pragma unroll
            for (int nt = 0; nt < 4; nt++) {
                long n0 = nBase + wn * 32 + nt * 8 + (lane & 3) * 2;
                float v0 = acc[mt][nt][half * 2 + 0] + __ldg(bias + n0);
                float v1 = acc[mt][nt][half * 2 + 1] + __ldg(bias + n0 + 1);
                if (mode == 2) {
                    const float2 rv = *(const float2*)(res + m * N + n0);
                    v0 += rv.x; v1 += rv.y;
                }
                if (mode == 1) {
                    v0 = 0.5f * v0 * (1.0f + erff(v0 * 0.70710678118654752f));
                    v1 = 0.5f * v1 * (1.0f + erff(v1 * 0.70710678118654752f));
                }
                if (C) {
                    *(float2*)(C + m * N + n0) = make_float2(v0, v1);
                }
                if (Ch) {
                    __nv_bfloat16 h0, l0, h1, l1;
                    split_bf16(v0, h0, l0);
                    split_bf16(v1, h1, l1);
                    *(__nv_bfloat162*)(Ch + m * N + n0) = __nv_bfloat162(h0, h1);
                    *(__nv_bfloat162*)(Cl + m * N + n0) = __nv_bfloat162(l0, l1);
                }
            }
        }
    }
}

// ---------------- attention ----------------------------------------------------
__global__ __launch_bounds__(256)
void attn_kernel(const float* __restrict__ q, const float* __restrict__ k,
                 const float* __restrict__ v, const int* __restrict__ mask,
                 __nv_bfloat16* __restrict__ ctx_hi, __nv_bfloat16* __restrict__ ctx_lo)
{
    __shared__ float Qs[16][64];
    __shared__ float Ks[32][66];
    __shared__ float Sc[16][SS];

    int b = blockIdx.z, h = blockIdx.y, qt = blockIdx.x;
    int tid = threadIdx.x;

    const float* qb = q + ((size_t)(b * SS + qt * 16)) * DD + h * DH;
    for (int i = tid; i < 16 * 64; i += 256) {
        int r = i >> 6, d = i & 63;
        Qs[r][d] = qb[(size_t)r * DD + d];
    }

    int qr = tid >> 4, tl = tid & 15;
    for (int t0 = 0; t0 < SS; t0 += 32) {
        const float* kb = k + ((size_t)(b * SS + t0)) * DD + h * DH;
        for (int i = tid; i < 32 * 64; i += 256) {
            int r = i >> 6, d = i & 63;
            Ks[r][d] = kb[(size_t)r * DD + d];
        }
        __syncthreads();
        #pragma unroll
        for (int half = 0; half < 2; half++) {
            int tt = tl + half * 16;
            float acc = 0.f;
            #pragma unroll
            for (int d = 0; d < 64; d++) acc += Qs[qr][d] * Ks[tt][d];
            Sc[qr][t0 + tt] = acc * 0.125f;
        }
        __syncthreads();
    }

    int warp = tid >> 5, lane = tid & 31;
    const int* mb = mask + b * SS;
    for (int r = warp; r < 16; r += 8) {
        float mx = -1e30f;
        for (int t = lane; t < SS; t += 32) mx = fmaxf(mx, Sc[r][t]);
        #pragma unroll
        for (int o = 16; o; o >>= 1) mx = fmaxf(mx, __shfl_xor_sync(0xffffffffu, mx, o));
        float Z = 0.f, Zm = 0.f;
        for (int t = lane; t < SS; t += 32) {
            float e = __expf(Sc[r][t] - mx);
            float mm = (float)mb[t];
            Sc[r][t] = e * mm;
            Z += e; Zm += e * mm;
        }
        #pragma unroll
        for (int o = 16; o; o >>= 1) {
            Z  += __shfl_xor_sync(0xffffffffu, Z,  o);
            Zm += __shfl_xor_sync(0xffffffffu, Zm, o);
        }
        float denom = fmaxf(Zm / Z, 1e-9f);
        float rcp = 1.0f / (Z * denom);
        for (int t = lane; t < SS; t += 32) Sc[r][t] *= rcp;
    }
    __syncthreads();

    int d = tid & 63, gidx = tid >> 6;
    float acc[4] = {0.f, 0.f, 0.f, 0.f};
    const float* vb = v + ((size_t)b * SS) * DD + h * DH + d;
    for (int t = 0; t < SS; t++) {
        float vv = vb[(size_t)t * DD];
        #pragma unroll
        for (int i = 0; i < 4; i++) acc[i] += Sc[gidx * 4 + i][t] * vv;
    }
    size_t cb = ((size_t)(b * SS + qt * 16)) * DD + h * DH + d;
    #pragma unroll
    for (int i = 0; i < 4; i++) {
        __nv_bfloat16 hi, lo; split_bf16(acc[i], hi, lo);
        ctx_hi[cb + (size_t)(gidx * 4 + i) * DD] = hi;
        ctx_lo[cb + (size_t)(gidx * 4 + i) * DD] = lo;
    }
}

// ---------------- pooling + L2 normalize ---------------------------------------
__global__ void pool_kernel(const float* __restrict__ h, const int* __restrict__ mask,
                            float* __restrict__ out)
{
    __shared__ float sent[DD];
    __shared__ float red[32];
    int b = blockIdx.x, tid = threadIdx.x;

    float ms = 0.f;
    for (int s = tid; s < SS; s += 256) ms += (float)mask[b * SS + s];
    ms = blockReduceSum(ms, red);
    float inv = 1.0f / fmaxf(ms, 1e-6f);

    for (int d = tid; d < DD; d += 256) {
        float a = 0.f;
        const float* hp = h + ((size_t)b * SS) * DD + d;
        const int* mp = mask + b * SS;
        for (int s = 0; s < SS; s++) a += hp[(size_t)s * DD] * (float)mp[s];
        sent[d] = a * inv;
    }
    __syncthreads();
    float sq = 0.f;
    for (int d = tid; d < DD; d += 256) sq += sent[d] * sent[d];
    sq = blockReduceSum(sq, red);
    float rn = 1.0f / fmaxf(sqrtf(sq), 1e-12f);
    for (int d = tid; d < DD; d += 256) out[b * DD + d] = sent[d] * rn;
}

// ---------------- launch --------------------------------------------------------
extern "C" void kernel_launch(void* const* d_in, const int* in_sizes, int n_in,
                              void* d_out, int out_size)
{
    const int*   input_ids = (const int*)  d_in[0];
    const int*   amask     = (const int*)  d_in[1];
    const float* word_emb  = (const float*)d_in[2];
    const float* pos_emb   = (const float*)d_in[3];
    const float* type_emb  = (const float*)d_in[4];
    const float* emb_g     = (const float*)d_in[5];
    const float* emb_b     = (const float*)d_in[6];
    const float* Wq = (const float*)d_in[7];  const float* bq = (const float*)d_in[8];
    const float* Wk = (const float*)d_in[9];  const float* bk = (const float*)d_in[10];
    const float* Wv = (const float*)d_in[11]; const float* bv = (const float*)d_in[12];
    const float* Wo = (const float*)d_in[13]; const float* bo = (const float*)d_in[14];
    const float* ln1g = (const float*)d_in[15]; const float* ln1b = (const float*)d_in[16];
    const float* Wi = (const float*)d_in[17]; const float* bi = (const float*)d_in[18];
    const float* Wf = (const float*)d_in[19]; const float* bf = (const float*)d_in[20];
    const float* ln2g = (const float*)d_in[21]; const float* ln2b = (const float*)d_in[22];
    float* out = (float*)d_out;

    float *p_h, *p_q, *p_k, *p_v, *p_t1;
    __nv_bfloat16 *p_hh, *p_hl, *p_ch, *p_cl, *p_fh, *p_fl;
    __nv_bfloat16 *wq_h, *wq_l, *wk_h, *wk_l, *wv_h, *wv_l, *wo_h, *wo_l;
    __nv_bfloat16 *wi_h, *wi_l, *wf_h, *wf_l;
    cudaGetSymbolAddress((void**)&p_h,  g_h);
    cudaGetSymbolAddress((void**)&p_q,  g_q);
    cudaGetSymbolAddress((void**)&p_k,  g_k);
    cudaGetSymbolAddress((void**)&p_v,  g_v);
    cudaGetSymbolAddress((void**)&p_t1, g_t1);
    cudaGetSymbolAddress((void**)&p_hh, g_h_hi);
    cudaGetSymbolAddress((void**)&p_hl, g_h_lo);
    cudaGetSymbolAddress((void**)&p_ch, g_ctx_hi);
    cudaGetSymbolAddress((void**)&p_cl, g_ctx_lo);
    cudaGetSymbolAddress((void**)&p_fh, g_ff_hi);
    cudaGetSymbolAddress((void**)&p_fl, g_ff_lo);
    cudaGetSymbolAddress((void**)&wq_h, g_WqT_h); cudaGetSymbolAddress((void**)&wq_l, g_WqT_l);
    cudaGetSymbolAddress((void**)&wk_h, g_WkT_h); cudaGetSymbolAddress((void**)&wk_l, g_WkT_l);
    cudaGetSymbolAddress((void**)&wv_h, g_WvT_h); cudaGetSymbolAddress((void**)&wv_l, g_WvT_l);
    cudaGetSymbolAddress((void**)&wo_h, g_WoT_h); cudaGetSymbolAddress((void**)&wo_l, g_WoT_l);
    cudaGetSymbolAddress((void**)&wi_h, g_WiT_h); cudaGetSymbolAddress((void**)&wi_l, g_WiT_l);
    cudaGetSymbolAddress((void**)&wf_h, g_WfT_h); cudaGetSymbolAddress((void**)&wf_l, g_WfT_l);

    cudaFuncSetAttribute(gemm_mma, cudaFuncAttributeMaxDynamicSharedMemorySize, GEMM_SMEM);

    dim3 tb(32, 8);
    transpose_convert<<<dim3(DD/32,  DD/32,  LL), tb>>>(Wq, wq_h, wq_l, DD, DD);
    transpose_convert<<<dim3(DD/32,  DD/32,  LL), tb>>>(Wk, wk_h, wk_l, DD, DD);
    transpose_convert<<<dim3(DD/32,  DD/32,  LL), tb>>>(Wv, wv_h, wv_l, DD, DD);
    transpose_convert<<<dim3(DD/32,  DD/32,  LL), tb>>>(Wo, wo_h, wo_l, DD, DD);
    transpose_convert<<<dim3(FFD/32, DD/32,  LL), tb>>>(Wi, wi_h, wi_l, DD, FFD);
    transpose_convert<<<dim3(DD/32,  FFD/32, LL), tb>>>(Wf, wf_h, wf_l, FFD, DD);

    embed_ln_kernel<<<MTOK, 256>>>(input_ids, word_emb, pos_emb, type_emb,
                                   emb_g, emb_b, p_h, p_hh, p_hl);

    dim3 gD (DD  / 128, MTOK / 128);   // (6, 32)
    dim3 gFF(FFD / 128, MTOK / 128);   // (24, 32)

    for (int l = 0; l < LL; l++) {
        size_t wdd = (size_t)l * DD * DD;
        size_t wdf = (size_t)l * DD * FFD;

        gemm_mma<<<gD, 256, GEMM_SMEM>>>(p_hh, p_hl, wq_h + wdd, wq_l + wdd,
                                         bq + l * DD, nullptr, p_q, nullptr, nullptr,
                                         MTOK, DD, DD, 0);
        gemm_mma<<<gD, 256, GEMM_SMEM>>>(p_hh, p_hl, wk_h + wdd, wk_l + wdd,
                                         bk + l * DD, nullptr, p_k, nullptr, nullptr,
                                         MTOK, DD, DD, 0);
        gemm_mma<<<gD, 256, GEMM_SMEM>>>(p_hh, p_hl, wv_h + wdd, wv_l + wdd,
                                         bv + l * DD, nullptr, p_v, nullptr, nullptr,
                                         MTOK, DD, DD, 0);

        attn_kernel<<<dim3(SS / 16, HH, BB), 256>>>(p_q, p_k, p_v, amask, p_ch, p_cl);

        gemm_mma<<<gD, 256, GEMM_SMEM>>>(p_ch, p_cl, wo_h + wdd, wo_l + wdd,
                                         bo + l * DD, p_h, p_t1, nullptr, nullptr,
                                         MTOK, DD, DD, 2);
        layernorm_kernel<<<MTOK, 256>>>(p_t1, ln1g + l * DD, ln1b + l * DD,
                                        p_h, p_hh, p_hl);

        gemm_mma<<<gFF, 256, GEMM_SMEM>>>(p_hh, p_hl, wi_h + wdf, wi_l + wdf,
                                          bi + l * FFD, nullptr, nullptr, p_fh, p_fl,
                                          MTOK, FFD, DD, 1);
        gemm_mma<<<gD, 256, GEMM_SMEM>>>(p_fh, p_fl, wf_h + wdf, wf_l + wdf,
                                         bf + l * DD, p_h, p_t1, nullptr, nullptr,
                                         MTOK, DD, FFD, 2);
        layernorm_kernel<<<MTOK, 256>>>(p_t1, ln2g + l * DD, ln2b + l * DD,
                                        p_h, p_hh, p_hl);
    }

    pool_kernel<<<BB, 256>>>(p_h, amask, out);
}

// round 5
// speedup vs baseline: 2.0960x; 1.2966x over previous
#include <cuda_runtime.h>
#include <cuda_bf16.h>
#include <math.h>
#include <stdint.h>

#define BB 8
#define SS 512
#define DD 768
#define HH 12
#define DH 64
#define LL 12
#define FFD 3072
#define MTOK (BB*SS)

__device__ __align__(256) float g_h  [MTOK*DD];
__device__ __align__(256) float g_q  [MTOK*DD];
__device__ __align__(256) float g_k  [MTOK*DD];
__device__ __align__(256) float g_v  [MTOK*DD];
__device__ __align__(256) float g_t1 [MTOK*DD];

__device__ __align__(256) __nv_bfloat16 g_h_hi [MTOK*DD];
__device__ __align__(256) __nv_bfloat16 g_h_lo [MTOK*DD];
__device__ __align__(256) __nv_bfloat16 g_ctx_hi[MTOK*DD];
__device__ __align__(256) __nv_bfloat16 g_ctx_lo[MTOK*DD];
__device__ __align__(256) __nv_bfloat16 g_ff_hi[MTOK*FFD];
__device__ __align__(256) __nv_bfloat16 g_ff_lo[MTOK*FFD];

__device__ __align__(256) __nv_bfloat16 g_WqT_h[LL*DD*DD];
__device__ __align__(256) __nv_bfloat16 g_WqT_l[LL*DD*DD];
__device__ __align__(256) __nv_bfloat16 g_WkT_h[LL*DD*DD];
__device__ __align__(256) __nv_bfloat16 g_WkT_l[LL*DD*DD];
__device__ __align__(256) __nv_bfloat16 g_WvT_h[LL*DD*DD];
__device__ __align__(256) __nv_bfloat16 g_WvT_l[LL*DD*DD];
__device__ __align__(256) __nv_bfloat16 g_WoT_h[LL*DD*DD];
__device__ __align__(256) __nv_bfloat16 g_WoT_l[LL*DD*DD];
__device__ __align__(256) __nv_bfloat16 g_WiT_h[LL*DD*FFD];
__device__ __align__(256) __nv_bfloat16 g_WiT_l[LL*DD*FFD];
__device__ __align__(256) __nv_bfloat16 g_WfT_h[LL*DD*FFD];
__device__ __align__(256) __nv_bfloat16 g_WfT_l[LL*DD*FFD];

// ---------------- helpers ------------------------------------------------------
__device__ __forceinline__ uint32_t smem_u32(const void* p) {
    uint32_t a;
    asm("{ .reg .u64 t; cvta.to.shared.u64 t, %1; cvt.u32.u64 %0, t; }" : "=r"(a) : "l"(p));
    return a;
}
__device__ __forceinline__ uint32_t swz(uint32_t o) { return o ^ ((o >> 3) & 0x70); }
__device__ __forceinline__ void cpa16(uint32_t saddr, const void* g) {
    asm volatile("cp.async.cg.shared.global [%0], [%1], 16;" :: "r"(saddr), "l"(g));
}
__device__ __forceinline__ void cp_commit() {
    asm volatile("cp.async.commit_group;" ::: "memory");
}
template <int N>
__device__ __forceinline__ void cp_wait() {
    asm volatile("cp.async.wait_group %0;" :: "n"(N) : "memory");
}
__device__ __forceinline__ void ldsm4(uint32_t& r0, uint32_t& r1, uint32_t& r2, uint32_t& r3,
                                      uint32_t addr) {
    asm volatile("ldmatrix.sync.aligned.m8n8.x4.shared.b16 {%0,%1,%2,%3}, [%4];"
                 : "=r"(r0), "=r"(r1), "=r"(r2), "=r"(r3) : "r"(addr));
}
__device__ __forceinline__ void ldsm4t(uint32_t& r0, uint32_t& r1, uint32_t& r2, uint32_t& r3,
                                       uint32_t addr) {
    asm volatile("ldmatrix.sync.aligned.m8n8.x4.trans.shared.b16 {%0,%1,%2,%3}, [%4];"
                 : "=r"(r0), "=r"(r1), "=r"(r2), "=r"(r3) : "r"(addr));
}
__device__ __forceinline__ void mma_bf16(float* d, const uint32_t* a, const uint32_t* b) {
    asm volatile("mma.sync.aligned.m16n8k16.row.col.f32.bf16.bf16.f32 "
                 "{%0,%1,%2,%3}, {%4,%5,%6,%7}, {%8,%9}, {%0,%1,%2,%3};"
                 : "+f"(d[0]), "+f"(d[1]), "+f"(d[2]), "+f"(d[3])
                 : "r"(a[0]), "r"(a[1]), "r"(a[2]), "r"(a[3]), "r"(b[0]), "r"(b[1]));
}
__device__ __forceinline__ void split_bf16(float x, __nv_bfloat16& hi, __nv_bfloat16& lo) {
    hi = __float2bfloat16(x);
    lo = __float2bfloat16(x - __bfloat162float(hi));
}
__device__ __forceinline__ void pack2(float a, float b, uint32_t& ph, uint32_t& pl) {
    __nv_bfloat16 ha, la, hb, lb;
    split_bf16(a, ha, la); split_bf16(b, hb, lb);
    __nv_bfloat162 th(ha, hb), tl(la, lb);
    ph = *(uint32_t*)&th; pl = *(uint32_t*)&tl;
}
__device__ __forceinline__ float blockReduceSum(float v, float* red) {
    int lane = threadIdx.x & 31, w = threadIdx.x >> 5;
    #pragma unroll
    for (int o = 16; o; o >>= 1) v += __shfl_xor_sync(0xffffffffu, v, o);
    if (lane == 0) red[w] = v;
    __syncthreads();
    float t = (threadIdx.x < (blockDim.x >> 5)) ? red[threadIdx.x] : 0.f;
    if (w == 0) {
        #pragma unroll
        for (int o = 16; o; o >>= 1) t += __shfl_xor_sync(0xffffffffu, t, o);
        if (lane == 0) red[0] = t;
    }
    __syncthreads();
    return red[0];
}

// ---------------- weight transpose + split --------------------------------------
__global__ void transpose_convert(const float* __restrict__ W,
                                  __nv_bfloat16* __restrict__ Th,
                                  __nv_bfloat16* __restrict__ Tl, int K, int N)
{
    __shared__ float t[32][33];
    size_t base = (size_t)blockIdx.z * K * N;
    const float* src = W + base;
    int n0 = blockIdx.x * 32, k0 = blockIdx.y * 32;
    for (int i = threadIdx.y; i < 32; i += 8)
        t[i][threadIdx.x] = src[(size_t)(k0 + i) * N + n0 + threadIdx.x];
    __syncthreads();
    for (int i = threadIdx.y; i < 32; i += 8) {
        float v = t[threadIdx.x][i];
        __nv_bfloat16 hi, lo; split_bf16(v, hi, lo);
        size_t o = base + (size_t)(n0 + i) * K + k0 + threadIdx.x;
        Th[o] = hi; Tl[o] = lo;
    }
}

// ---------------- embedding / layernorm ------------------------------------------
__global__ void embed_ln_kernel(const int* __restrict__ ids, const float* __restrict__ we,
                                const float* __restrict__ pe, const float* __restrict__ te,
                                const float* __restrict__ gam, const float* __restrict__ bet,
                                float* __restrict__ out,
                                __nv_bfloat16* __restrict__ oh, __nv_bfloat16* __restrict__ ol)
{
    __shared__ float xs[DD];
    __shared__ float red[32];
    int tok = blockIdx.x, s = tok & (SS - 1), id = ids[tok], tid = threadIdx.x;
    const float* wrow = we + (size_t)id * DD;
    const float* prow = pe + (size_t)s * DD;
    float sum = 0.f;
    for (int d = tid; d < DD; d += 256) {
        float v = wrow[d] + prow[d] + te[d];
        xs[d] = v; sum += v;
    }
    float mu = blockReduceSum(sum, red) * (1.0f / DD);
    float vs = 0.f;
    for (int d = tid; d < DD; d += 256) { float dl = xs[d] - mu; vs += dl * dl; }
    float var = blockReduceSum(vs, red) * (1.0f / DD);
    float r = rsqrtf(var + 1e-12f);
    size_t ro = (size_t)tok * DD;
    for (int d = tid; d < DD; d += 256) {
        float o = (xs[d] - mu) * r * gam[d] + bet[d];
        out[ro + d] = o;
        __nv_bfloat16 hi, lo; split_bf16(o, hi, lo);
        oh[ro + d] = hi; ol[ro + d] = lo;
    }
}

__global__ void layernorm_kernel(const float* __restrict__ x, const float* __restrict__ gam,
                                 const float* __restrict__ bet, float* __restrict__ out,
                                 __nv_bfloat16* __restrict__ oh, __nv_bfloat16* __restrict__ ol)
{
    __shared__ float xs[DD];
    __shared__ float red[32];
    int row = blockIdx.x, tid = threadIdx.x;
    const float* xr = x + (size_t)row * DD;
    float sum = 0.f;
    for (int d = tid; d < DD; d += 256) { float v = xr[d]; xs[d] = v; sum += v; }
    float mu = blockReduceSum(sum, red) * (1.0f / DD);
    float vs = 0.f;
    for (int d = tid; d < DD; d += 256) { float dl = xs[d] - mu; vs += dl * dl; }
    float var = blockReduceSum(vs, red) * (1.0f / DD);
    float r = rsqrtf(var + 1e-12f);
    size_t ro = (size_t)row * DD;
    for (int d = tid; d < DD; d += 256) {
        float o = (xs[d] - mu) * r * gam[d] + bet[d];
        out[ro + d] = o;
        __nv_bfloat16 hi, lo; split_bf16(o, hi, lo);
        oh[ro + d] = hi; ol[ro + d] = lo;
    }
}

// ---------------- GEMM: 3-stage cp.async, 2 CTA/SM -------------------------------
#define GSTG 3
#define GEMM_SMEM (GSTG*32768 + 1024)

__global__ __launch_bounds__(256, 2)
void gemm_mma(const __nv_bfloat16* __restrict__ Ah, const __nv_bfloat16* __restrict__ Al,
              const __nv_bfloat16* __restrict__ Bh, const __nv_bfloat16* __restrict__ Bl,
              const float* __restrict__ bias, const float* __restrict__ res,
              float* __restrict__ C,
              __nv_bfloat16* __restrict__ Ch, __nv_bfloat16* __restrict__ Cl,
              int M, int N, int K, int mode)
{
    extern __shared__ char dsm[];
    uint32_t raw = smem_u32(dsm);
    uint32_t s0 = (raw + 1023) & ~1023u;

    int tid = threadIdx.x, wid = tid >> 5, lane = tid & 31;
    int wm = wid & 1, wn = wid >> 1;
    long mBase = (long)blockIdx.y * 128;
    long nBase = (long)blockIdx.x * 128;

    float acc[4][4][4];
    #pragma unroll
    for (int i = 0; i < 4; i++)
        #pragma unroll
        for (int j = 0; j < 4; j++)
            #pragma unroll
            for (int q = 0; q < 4; q++) acc[i][j][q] = 0.f;

    int lrow = tid >> 1, lkc0 = (tid & 1) * 2;
    const __nv_bfloat16* Ahp = Ah + (size_t)(mBase + lrow) * K;
    const __nv_bfloat16* Alp = Al + (size_t)(mBase + lrow) * K;
    const __nv_bfloat16* Bhp = Bh + (size_t)(nBase + lrow) * K;
    const __nv_bfloat16* Blp = Bl + (size_t)(nBase + lrow) * K;
    uint32_t sw0 = swz(lrow * 64 + lkc0 * 16);
    uint32_t sw1 = swz(lrow * 64 + (lkc0 + 1) * 16);
    const int nIt = K / 32;

    #pragma unroll 1
    for (int pf = 0; pf < 2; pf++) {
        uint32_t sb = s0 + pf * 32768;
        int k0 = pf * 32 + lkc0 * 8;
        cpa16(sb + sw0, Ahp + k0);          cpa16(sb + sw1, Ahp + k0 + 8);
        cpa16(sb + 8192 + sw0, Alp + k0);   cpa16(sb + 8192 + sw1, Alp + k0 + 8);
        cpa16(sb + 16384 + sw0, Bhp + k0);  cpa16(sb + 16384 + sw1, Bhp + k0 + 8);
        cpa16(sb + 24576 + sw0, Blp + k0);  cpa16(sb + 24576 + sw1, Blp + k0 + 8);
        cp_commit();
    }

    #pragma unroll 1
    for (int it = 0; it < nIt; ++it) {
        if (it < nIt - 1) cp_wait<1>(); else cp_wait<0>();
        __syncthreads();
        if (it + 2 < nIt) {
            uint32_t sb = s0 + ((it + 2) % GSTG) * 32768;
            int k0 = (it + 2) * 32 + lkc0 * 8;
            cpa16(sb + sw0, Ahp + k0);          cpa16(sb + sw1, Ahp + k0 + 8);
            cpa16(sb + 8192 + sw0, Alp + k0);   cpa16(sb + 8192 + sw1, Alp + k0 + 8);
            cpa16(sb + 16384 + sw0, Bhp + k0);  cpa16(sb + 16384 + sw1, Bhp + k0 + 8);
            cpa16(sb + 24576 + sw0, Blp + k0);  cpa16(sb + 24576 + sw1, Blp + k0 + 8);
            cp_commit();
        }
        uint32_t base = s0 + (it % GSTG) * 32768;
        #pragma unroll
        for (int ks = 0; ks < 2; ks++) {
            uint32_t kcol = (ks * 2 + (lane >> 4)) * 16;
            int brow = wn * 32 + (lane & 15);
            uint32_t bh[4][2], bl[4][2];
            #pragma unroll
            for (int n2 = 0; n2 < 2; n2++) {
                uint32_t r0, r1, r2, r3;
                ldsm4(r0, r1, r2, r3, base + 16384 + swz((brow + n2 * 16) * 64 + kcol));
                bh[n2*2][0] = r0; bh[n2*2][1] = r2; bh[n2*2+1][0] = r1; bh[n2*2+1][1] = r3;
                ldsm4(r0, r1, r2, r3, base + 24576 + swz((brow + n2 * 16) * 64 + kcol));
                bl[n2*2][0] = r0; bl[n2*2][1] = r2; bl[n2*2+1][0] = r1; bl[n2*2+1][1] = r3;
            }
            int arow = wm * 64 + (lane & 15);
            #pragma unroll
            for (int mt = 0; mt < 4; mt++) {
                uint32_t a[4];
                ldsm4(a[0], a[1], a[2], a[3], base + swz((arow + mt * 16) * 64 + kcol));
                #pragma unroll
                for (int nt = 0; nt < 4; nt++) mma_bf16(acc[mt][nt], a, bh[nt]);
                #pragma unroll
                for (int nt = 0; nt < 4; nt++) mma_bf16(acc[mt][nt], a, bl[nt]);
                ldsm4(a[0], a[1], a[2], a[3], base + 8192 + swz((arow + mt * 16) * 64 + kcol));
                #pragma unroll
                for (int nt = 0; nt < 4; nt++) mma_bf16(acc[mt][nt], a, bh[nt]);
            }
        }
    }

    #pragma unroll
    for (int mt = 0; mt < 4; mt++) {
        #pragma unroll
        for (int half = 0; half < 2; half++) {
            long m = mBase + wm * 64 + mt * 16 + (lane >> 2) + half * 8;
            #pragma unroll
            for (int nt = 0; nt < 4; nt++) {
                long n0 = nBase + wn * 32 + nt * 8 + (lane & 3) * 2;
                float v0 = acc[mt][nt][half * 2] + __ldg(bias + n0);
                float v1 = acc[mt][nt][half * 2 + 1] + __ldg(bias + n0 + 1);
                if (mode == 2) {
                    float2 rv = *(const float2*)(res + m * N + n0);
                    v0 += rv.x; v1 += rv.y;
                    *(float2*)(C + m * N + n0) = make_float2(v0, v1);
                } else if (mode == 1) {
                    v0 = 0.5f * v0 * (1.0f + erff(v0 * 0.70710678118654752f));
                    v1 = 0.5f * v1 * (1.0f + erff(v1 * 0.70710678118654752f));
                    uint32_t ph, pl; pack2(v0, v1, ph, pl);
                    *(uint32_t*)(Ch + m * N + n0) = ph;
                    *(uint32_t*)(Cl + m * N + n0) = pl;
                } else {
                    *(float2*)(C + m * N + n0) = make_float2(v0, v1);
                }
            }
        }
    }
}

// ---------------- flash attention (mma.sync, split-bf16) -------------------------
#define A_QH 0
#define A_QL 16384
#define A_KH 32768
#define A_KL 40960
#define A_VH 49152
#define A_VL 57344
#define A_MK 65536
#define ATTN_SMEM (65536 + 2048 + 1024)

__global__ __launch_bounds__(256, 1)
void attn_flash(const float* __restrict__ q, const float* __restrict__ k,
                const float* __restrict__ v, const int* __restrict__ mask,
                __nv_bfloat16* __restrict__ ctx_h, __nv_bfloat16* __restrict__ ctx_l)
{
    extern __shared__ char dsm[];
    uint32_t raw = smem_u32(dsm);
    uint32_t s0 = (raw + 1023) & ~1023u;
    char* sm = dsm + (s0 - raw);

    int b = blockIdx.z, h = blockIdx.y, qt = blockIdx.x;
    int tid = threadIdx.x, wid = tid >> 5, lane = tid & 31;
    int q0 = b * SS + qt * 128;
    int k0g = b * SS;

    float* maskf = (float*)(sm + A_MK);
    for (int i = tid; i < SS; i += 256) maskf[i] = (float)mask[b * SS + i];

    // Q: scale 1/8, split, store swizzled (rows 128B)
    for (int i = tid; i < 128 * 16; i += 256) {
        int row = i >> 4, c4 = i & 15;
        float4 qv = *(const float4*)(q + (size_t)(q0 + row) * DD + h * DH + c4 * 4);
        uint32_t h0, l0, h1, l1;
        pack2(qv.x * 0.125f, qv.y * 0.125f, h0, l0);
        pack2(qv.z * 0.125f, qv.w * 0.125f, h1, l1);
        uint32_t sw = swz(row * 128 + c4 * 8);
        *(uint32_t*)(sm + A_QH + sw) = h0; *(uint32_t*)(sm + A_QH + sw + 4) = h1;
        *(uint32_t*)(sm + A_QL + sw) = l0; *(uint32_t*)(sm + A_QL + sw + 4) = l1;
    }
    __syncthreads();

    uint32_t qh[4][4], ql[4][4];
    {
        int qr = wid * 16 + (lane & 15);
        #pragma unroll
        for (int ks = 0; ks < 4; ks++) {
            uint32_t o2 = swz(qr * 128 + (ks * 2 + (lane >> 4)) * 16);
            ldsm4(qh[ks][0], qh[ks][1], qh[ks][2], qh[ks][3], s0 + A_QH + o2);
            ldsm4(ql[ks][0], ql[ks][1], ql[ks][2], ql[ks][3], s0 + A_QL + o2);
        }
    }

    float M[2] = {-1e30f, -1e30f}, Zs[2] = {0.f, 0.f}, Zm[2] = {0.f, 0.f};
    float o[8][4];
    #pragma unroll
    for (int i = 0; i < 8; i++)
        #pragma unroll
        for (int j = 0; j < 4; j++) o[i][j] = 0.f;

    #pragma unroll 1
    for (int ch = 0; ch < 8; ch++) {
        __syncthreads();
        for (int i = tid; i < 64 * 16; i += 256) {
            int row = i >> 4, c4 = i & 15;
            size_t g = (size_t)(k0g + ch * 64 + row) * DD + h * DH + c4 * 4;
            uint32_t sw = swz(row * 128 + c4 * 8);
            float4 kv = *(const float4*)(k + g);
            uint32_t h0, l0, h1, l1;
            pack2(kv.x, kv.y, h0, l0); pack2(kv.z, kv.w, h1, l1);
            *(uint32_t*)(sm + A_KH + sw) = h0; *(uint32_t*)(sm + A_KH + sw + 4) = h1;
            *(uint32_t*)(sm + A_KL + sw) = l0; *(uint32_t*)(sm + A_KL + sw + 4) = l1;
            float4 vv = *(const float4*)(v + g);
            pack2(vv.x, vv.y, h0, l0); pack2(vv.z, vv.w, h1, l1);
            *(uint32_t*)(sm + A_VH + sw) = h0; *(uint32_t*)(sm + A_VH + sw + 4) = h1;
            *(uint32_t*)(sm + A_VL + sw) = l0; *(uint32_t*)(sm + A_VL + sw + 4) = l1;
        }
        __syncthreads();

        float s[8][4];
        #pragma unroll
        for (int i = 0; i < 8; i++)
            #pragma unroll
            for (int j = 0; j < 4; j++) s[i][j] = 0.f;

        #pragma unroll
        for (int n4 = 0; n4 < 4; n4++) {
            int br = n4 * 16 + (lane & 15);
            #pragma unroll
            for (int ks = 0; ks < 4; ks++) {
                uint32_t kcol = (ks * 2 + (lane >> 4)) * 16;
                uint32_t r0, r1, r2, r3;
                uint32_t bh0[2], bh1[2], bl0[2], bl1[2];
                ldsm4(r0, r1, r2, r3, s0 + A_KH + swz(br * 128 + kcol));
                bh0[0] = r0; bh0[1] = r2; bh1[0] = r1; bh1[1] = r3;
                ldsm4(r0, r1, r2, r3, s0 + A_KL + swz(br * 128 + kcol));
                bl0[0] = r0; bl0[1] = r2; bl1[0] = r1; bl1[1] = r3;
                mma_bf16(s[n4*2], qh[ks], bh0);  mma_bf16(s[n4*2+1], qh[ks], bh1);
                mma_bf16(s[n4*2], qh[ks], bl0);  mma_bf16(s[n4*2+1], qh[ks], bl1);
                mma_bf16(s[n4*2], ql[ks], bh0);  mma_bf16(s[n4*2+1], ql[ks], bh1);
            }
        }

        // online masked softmax per row group g (rows lane>>2 and +8)
        #pragma unroll
        for (int g = 0; g < 2; g++) {
            float mx = -1e30f;
            #pragma unroll
            for (int nt = 0; nt < 8; nt++)
                mx = fmaxf(mx, fmaxf(s[nt][2*g], s[nt][2*g+1]));
            mx = fmaxf(mx, __shfl_xor_sync(0xffffffffu, mx, 1));
            mx = fmaxf(mx, __shfl_xor_sync(0xffffffffu, mx, 2));
            float Mn = fmaxf(M[g], mx);
            float fac = __expf(M[g] - Mn);
            float zc = 0.f, zmc = 0.f;
            #pragma unroll
            for (int nt = 0; nt < 8; nt++) {
                #pragma unroll
                for (int e = 0; e < 2; e++) {
                    int col = ch * 64 + nt * 8 + (lane & 3) * 2 + e;
                    float ex = __expf(s[nt][2*g+e] - Mn);
                    float mm = maskf[col];
                    zc += ex; zmc += ex * mm;
                    s[nt][2*g+e] = ex * mm;
                }
            }
            zc += __shfl_xor_sync(0xffffffffu, zc, 1);
            zc += __shfl_xor_sync(0xffffffffu, zc, 2);
            zmc += __shfl_xor_sync(0xffffffffu, zmc, 1);
            zmc += __shfl_xor_sync(0xffffffffu, zmc, 2);
            Zs[g] = Zs[g] * fac + zc;
            Zm[g] = Zm[g] * fac + zmc;
            M[g] = Mn;
            #pragma unroll
            for (int nt = 0; nt < 8; nt++) { o[nt][2*g] *= fac; o[nt][2*g+1] *= fac; }
        }

        // P fragments (C layout -> A layout trick)
        uint32_t ah[4][4], al[4][4];
        #pragma unroll
        for (int kt = 0; kt < 4; kt++) {
            pack2(s[2*kt][0],   s[2*kt][1],   ah[kt][0], al[kt][0]);
            pack2(s[2*kt][2],   s[2*kt][3],   ah[kt][1], al[kt][1]);
            pack2(s[2*kt+1][0], s[2*kt+1][1], ah[kt][2], al[kt][2]);
            pack2(s[2*kt+1][2], s[2*kt+1][3], ah[kt][3], al[kt][3]);
        }

        // P @ V : V stored [t][d], ldmatrix.trans gives B=[d][t]
        #pragma unroll
        for (int n4 = 0; n4 < 4; n4++) {
            #pragma unroll
            for (int kt = 0; kt < 4; kt++) {
                uint32_t addr = swz((kt * 16 + (lane & 15)) * 128 + n4 * 32 + (lane >> 4) * 16);
                uint32_t r0, r1, r2, r3;
                uint32_t bh0[2], bh1[2], bl0[2], bl1[2];
                ldsm4t(r0, r1, r2, r3, s0 + A_VH + addr);
                bh0[0] = r0; bh0[1] = r1; bh1[0] = r2; bh1[1] = r3;
                ldsm4t(r0, r1, r2, r3, s0 + A_VL + addr);
                bl0[0] = r0; bl0[1] = r1; bl1[0] = r2; bl1[1] = r3;
                mma_bf16(o[n4*2], ah[kt], bh0);  mma_bf16(o[n4*2+1], ah[kt], bh1);
                mma_bf16(o[n4*2], ah[kt], bl0);  mma_bf16(o[n4*2+1], ah[kt], bl1);
                mma_bf16(o[n4*2], al[kt], bh0);  mma_bf16(o[n4*2+1], al[kt], bh1);
            }
        }
    }

    #pragma unroll
    for (int g = 0; g < 2; g++) {
        float den = fmaxf(Zm[g], 1e-9f * Zs[g]);
        float rcp = 1.0f / den;
        size_t row = q0 + wid * 16 + (lane >> 2) + g * 8;
        #pragma unroll
        for (int nt = 0; nt < 8; nt++) {
            int col = h * DH + nt * 8 + (lane & 3) * 2;
            uint32_t ph, pl;
            pack2(o[nt][2*g] * rcp, o[nt][2*g+1] * rcp, ph, pl);
            *(uint32_t*)(ctx_h + row * DD + col) = ph;
            *(uint32_t*)(ctx_l + row * DD + col) = pl;
        }
    }
}

// ---------------- pool + normalize ------------------------------------------------
__global__ void pool_kernel(const float* __restrict__ h, const int* __restrict__ mask,
                            float* __restrict__ out)
{
    __shared__ float sent[DD];
    __shared__ float red[32];
    int b = blockIdx.x, tid = threadIdx.x;
    float ms = 0.f;
    for (int s = tid; s < SS; s += 256) ms += (float)mask[b * SS + s];
    ms = blockReduceSum(ms, red);
    float inv = 1.0f / fmaxf(ms, 1e-6f);
    for (int d = tid; d < DD; d += 256) {
        float a = 0.f;
        const float* hp = h + ((size_t)b * SS) * DD + d;
        const int* mp = mask + b * SS;
        for (int s = 0; s < SS; s++) a += hp[(size_t)s * DD] * (float)mp[s];
        sent[d] = a * inv;
    }
    __syncthreads();
    float sq = 0.f;
    for (int d = tid; d < DD; d += 256) sq += sent[d] * sent[d];
    sq = blockReduceSum(sq, red);
    float rn = 1.0f / fmaxf(sqrtf(sq), 1e-12f);
    for (int d = tid; d < DD; d += 256) out[b * DD + d] = sent[d] * rn;
}

// ---------------- launch -----------------------------------------------------------
extern "C" void kernel_launch(void* const* d_in, const int* in_sizes, int n_in,
                              void* d_out, int out_size)
{
    const int*   input_ids = (const int*)  d_in[0];
    const int*   amask     = (const int*)  d_in[1];
    const float* word_emb  = (const float*)d_in[2];
    const float* pos_emb   = (const float*)d_in[3];
    const float* type_emb  = (const float*)d_in[4];
    const float* emb_g     = (const float*)d_in[5];
    const float* emb_b     = (const float*)d_in[6];
    const float* Wq = (const float*)d_in[7];  const float* bq = (const float*)d_in[8];
    const float* Wk = (const float*)d_in[9];  const float* bk = (const float*)d_in[10];
    const float* Wv = (const float*)d_in[11]; const float* bv = (const float*)d_in[12];
    const float* Wo = (const float*)d_in[13]; const float* bo = (const float*)d_in[14];
    const float* ln1g = (const float*)d_in[15]; const float* ln1b = (const float*)d_in[16];
    const float* Wi = (const float*)d_in[17]; const float* bi = (const float*)d_in[18];
    const float* Wf = (const float*)d_in[19]; const float* bf = (const float*)d_in[20];
    const float* ln2g = (const float*)d_in[21]; const float* ln2b = (const float*)d_in[22];
    float* out = (float*)d_out;

    float *p_h, *p_q, *p_k, *p_v, *p_t1;
    __nv_bfloat16 *p_hh, *p_hl, *p_ch, *p_cl, *p_fh, *p_fl;
    __nv_bfloat16 *wq_h, *wq_l, *wk_h, *wk_l, *wv_h, *wv_l, *wo_h, *wo_l;
    __nv_bfloat16 *wi_h, *wi_l, *wf_h, *wf_l;
    cudaGetSymbolAddress((void**)&p_h,  g_h);
    cudaGetSymbolAddress((void**)&p_q,  g_q);
    cudaGetSymbolAddress((void**)&p_k,  g_k);
    cudaGetSymbolAddress((void**)&p_v,  g_v);
    cudaGetSymbolAddress((void**)&p_t1, g_t1);
    cudaGetSymbolAddress((void**)&p_hh, g_h_hi);
    cudaGetSymbolAddress((void**)&p_hl, g_h_lo);
    cudaGetSymbolAddress((void**)&p_ch, g_ctx_hi);
    cudaGetSymbolAddress((void**)&p_cl, g_ctx_lo);
    cudaGetSymbolAddress((void**)&p_fh, g_ff_hi);
    cudaGetSymbolAddress((void**)&p_fl, g_ff_lo);
    cudaGetSymbolAddress((void**)&wq_h, g_WqT_h); cudaGetSymbolAddress((void**)&wq_l, g_WqT_l);
    cudaGetSymbolAddress((void**)&wk_h, g_WkT_h); cudaGetSymbolAddress((void**)&wk_l, g_WkT_l);
    cudaGetSymbolAddress((void**)&wv_h, g_WvT_h); cudaGetSymbolAddress((void**)&wv_l, g_WvT_l);
    cudaGetSymbolAddress((void**)&wo_h, g_WoT_h); cudaGetSymbolAddress((void**)&wo_l, g_WoT_l);
    cudaGetSymbolAddress((void**)&wi_h, g_WiT_h); cudaGetSymbolAddress((void**)&wi_l, g_WiT_l);
    cudaGetSymbolAddress((void**)&wf_h, g_WfT_h); cudaGetSymbolAddress((void**)&wf_l, g_WfT_l);

    cudaFuncSetAttribute(gemm_mma, cudaFuncAttributeMaxDynamicSharedMemorySize, GEMM_SMEM);
    cudaFuncSetAttribute(attn_flash, cudaFuncAttributeMaxDynamicSharedMemorySize, ATTN_SMEM);

    dim3 tb(32, 8);
    transpose_convert<<<dim3(DD/32,  DD/32,  LL), tb>>>(Wq, wq_h, wq_l, DD, DD);
    transpose_convert<<<dim3(DD/32,  DD/32,  LL), tb>>>(Wk, wk_h, wk_l, DD, DD);
    transpose_convert<<<dim3(DD/32,  DD/32,  LL), tb>>>(Wv, wv_h, wv_l, DD, DD);
    transpose_convert<<<dim3(DD/32,  DD/32,  LL), tb>>>(Wo, wo_h, wo_l, DD, DD);
    transpose_convert<<<dim3(FFD/32, DD/32,  LL), tb>>>(Wi, wi_h, wi_l, DD, FFD);
    transpose_convert<<<dim3(DD/32,  FFD/32, LL), tb>>>(Wf, wf_h, wf_l, FFD, DD);

    embed_ln_kernel<<<MTOK, 256>>>(input_ids, word_emb, pos_emb, type_emb,
                                   emb_g, emb_b, p_h, p_hh, p_hl);

    dim3 gD (DD  / 128, MTOK / 128);
    dim3 gFF(FFD / 128, MTOK / 128);

    for (int l = 0; l < LL; l++) {
        size_t wdd = (size_t)l * DD * DD;
        size_t wdf = (size_t)l * DD * FFD;

        gemm_mma<<<gD, 256, GEMM_SMEM>>>(p_hh, p_hl, wq_h + wdd, wq_l + wdd,
                                         bq + l * DD, nullptr, p_q, nullptr, nullptr,
                                         MTOK, DD, DD, 0);
        gemm_mma<<<gD, 256, GEMM_SMEM>>>(p_hh, p_hl, wk_h + wdd, wk_l + wdd,
                                         bk + l * DD, nullptr, p_k, nullptr, nullptr,
                                         MTOK, DD, DD, 0);
        gemm_mma<<<gD, 256, GEMM_SMEM>>>(p_hh, p_hl, wv_h + wdd, wv_l + wdd,
                                         bv + l * DD, nullptr, p_v, nullptr, nullptr,
                                         MTOK, DD, DD, 0);

        attn_flash<<<dim3(4, HH, BB), 256, ATTN_SMEM>>>(p_q, p_k, p_v, amask, p_ch, p_cl);

        gemm_mma<<<gD, 256, GEMM_SMEM>>>(p_ch, p_cl, wo_h + wdd, wo_l + wdd,
                                         bo + l * DD, p_h, p_t1, nullptr, nullptr,
                                         MTOK, DD, DD, 2);
        layernorm_kernel<<<MTOK, 256>>>(p_t1, ln1g + l * DD, ln1b + l * DD,
                                        p_h, p_hh, p_hl);

        gemm_mma<<<gFF, 256, GEMM_SMEM>>>(p_hh, p_hl, wi_h + wdf, wi_l + wdf,
                                          bi + l * FFD, nullptr, nullptr, p_fh, p_fl,
                                          MTOK, FFD, DD, 1);
        gemm_mma<<<gD, 256, GEMM_SMEM>>>(p_fh, p_fl, wf_h + wdf, wf_l + wdf,
                                         bf + l * DD, p_h, p_t1, nullptr, nullptr,
                                         MTOK, DD, FFD, 2);
        layernorm_kernel<<<MTOK, 256>>>(p_t1, ln2g + l * DD, ln2b + l * DD,
                                        p_h, p_hh, p_hl);
    }

    pool_kernel<<<BB, 256>>>(p_h, amask, out);
}

// round 6
// speedup vs baseline: 2.3725x; 1.1319x over previous
#include <cuda_runtime.h>
#include <cuda_bf16.h>
#include <math.h>
#include <stdint.h>

#define BB 8
#define SS 512
#define DD 768
#define HH 12
#define DH 64
#define LL 12
#define FFD 3072
#define MTOK (BB*SS)
#define NQKV 2304

__device__ __align__(256) float g_h  [MTOK*DD];
__device__ __align__(256) float g_t1 [MTOK*DD];

__device__ __align__(256) __nv_bfloat16 g_h_hi [MTOK*DD];
__device__ __align__(256) __nv_bfloat16 g_h_lo [MTOK*DD];
__device__ __align__(256) __nv_bfloat16 g_qkv_h[MTOK*NQKV];
__device__ __align__(256) __nv_bfloat16 g_qkv_l[MTOK*NQKV];
__device__ __align__(256) __nv_bfloat16 g_ctx_hi[MTOK*DD];
__device__ __align__(256) __nv_bfloat16 g_ctx_lo[MTOK*DD];
__device__ __align__(256) __nv_bfloat16 g_ff_hi[MTOK*FFD];
__device__ __align__(256) __nv_bfloat16 g_ff_lo[MTOK*FFD];

__device__ __align__(256) __nv_bfloat16 g_Wqkv_h[LL*NQKV*DD];
__device__ __align__(256) __nv_bfloat16 g_Wqkv_l[LL*NQKV*DD];
__device__ __align__(256) __nv_bfloat16 g_WoT_h[LL*DD*DD];
__device__ __align__(256) __nv_bfloat16 g_WoT_l[LL*DD*DD];
__device__ __align__(256) __nv_bfloat16 g_WiT_h[LL*DD*FFD];
__device__ __align__(256) __nv_bfloat16 g_WiT_l[LL*DD*FFD];
__device__ __align__(256) __nv_bfloat16 g_WfT_h[LL*DD*FFD];
__device__ __align__(256) __nv_bfloat16 g_WfT_l[LL*DD*FFD];
__device__ __align__(256) float g_bqkv[LL*NQKV];

// ---------------- helpers ------------------------------------------------------
__device__ __forceinline__ uint32_t smem_u32(const void* p) {
    uint32_t a;
    asm("{ .reg .u64 t; cvta.to.shared.u64 t, %1; cvt.u32.u64 %0, t; }" : "=r"(a) : "l"(p));
    return a;
}
__device__ __forceinline__ uint32_t swz(uint32_t o) { return o ^ ((o >> 3) & 0x70); }
__device__ __forceinline__ void cpa16(uint32_t saddr, const void* g) {
    asm volatile("cp.async.cg.shared.global [%0], [%1], 16;" :: "r"(saddr), "l"(g));
}
__device__ __forceinline__ void cp_commit() {
    asm volatile("cp.async.commit_group;" ::: "memory");
}
template <int N>
__device__ __forceinline__ void cp_wait() {
    asm volatile("cp.async.wait_group %0;" :: "n"(N) : "memory");
}
__device__ __forceinline__ void ldsm4(uint32_t& r0, uint32_t& r1, uint32_t& r2, uint32_t& r3,
                                      uint32_t addr) {
    asm volatile("ldmatrix.sync.aligned.m8n8.x4.shared.b16 {%0,%1,%2,%3}, [%4];"
                 : "=r"(r0), "=r"(r1), "=r"(r2), "=r"(r3) : "r"(addr));
}
__device__ __forceinline__ void ldsm4t(uint32_t& r0, uint32_t& r1, uint32_t& r2, uint32_t& r3,
                                       uint32_t addr) {
    asm volatile("ldmatrix.sync.aligned.m8n8.x4.trans.shared.b16 {%0,%1,%2,%3}, [%4];"
                 : "=r"(r0), "=r"(r1), "=r"(r2), "=r"(r3) : "r"(addr));
}
__device__ __forceinline__ void mma_bf16(float* d, const uint32_t* a, const uint32_t* b) {
    asm volatile("mma.sync.aligned.m16n8k16.row.col.f32.bf16.bf16.f32 "
                 "{%0,%1,%2,%3}, {%4,%5,%6,%7}, {%8,%9}, {%0,%1,%2,%3};"
                 : "+f"(d[0]), "+f"(d[1]), "+f"(d[2]), "+f"(d[3])
                 : "r"(a[0]), "r"(a[1]), "r"(a[2]), "r"(a[3]), "r"(b[0]), "r"(b[1]));
}
__device__ __forceinline__ void split_bf16(float x, __nv_bfloat16& hi, __nv_bfloat16& lo) {
    hi = __float2bfloat16(x);
    lo = __float2bfloat16(x - __bfloat162float(hi));
}
__device__ __forceinline__ void pack2(float a, float b, uint32_t& ph, uint32_t& pl) {
    __nv_bfloat16 ha, la, hb, lb;
    split_bf16(a, ha, la); split_bf16(b, hb, lb);
    __nv_bfloat162 th(ha, hb), tl(la, lb);
    ph = *(uint32_t*)&th; pl = *(uint32_t*)&tl;
}
__device__ __forceinline__ float blockReduceSum(float v, float* red) {
    int lane = threadIdx.x & 31, w = threadIdx.x >> 5;
    #pragma unroll
    for (int o = 16; o; o >>= 1) v += __shfl_xor_sync(0xffffffffu, v, o);
    if (lane == 0) red[w] = v;
    __syncthreads();
    float t = (threadIdx.x < (blockDim.x >> 5)) ? red[threadIdx.x] : 0.f;
    if (w == 0) {
        #pragma unroll
        for (int o = 16; o; o >>= 1) t += __shfl_xor_sync(0xffffffffu, t, o);
        if (lane == 0) red[0] = t;
    }
    __syncthreads();
    return red[0];
}

// ---------------- ALL weight transposes, one launch ------------------------------
__global__ void trans_all(const float* __restrict__ Wq, const float* __restrict__ Wk,
                          const float* __restrict__ Wv, const float* __restrict__ Wo,
                          const float* __restrict__ Wi, const float* __restrict__ Wf)
{
    __shared__ float tsm[32][33];
    int t = blockIdx.x;
    int l = t / 6912, r = t % 6912;
    const float* src; __nv_bfloat16 *dh, *dl;
    int K, N, rowoff, nx, ky;
    if (r < 1728) {
        int w = r / 576, q2 = r % 576;
        src = (w == 0 ? Wq : w == 1 ? Wk : Wv) + (size_t)l * DD * DD;
        dh = g_Wqkv_h + (size_t)l * NQKV * DD; dl = g_Wqkv_l + (size_t)l * NQKV * DD;
        K = DD; N = DD; rowoff = w * DD; ky = q2 / 24; nx = q2 % 24;
    } else if (r < 2304) {
        int q2 = r - 1728;
        src = Wo + (size_t)l * DD * DD;
        dh = g_WoT_h + (size_t)l * DD * DD; dl = g_WoT_l + (size_t)l * DD * DD;
        K = DD; N = DD; rowoff = 0; ky = q2 / 24; nx = q2 % 24;
    } else if (r < 4608) {
        int q2 = r - 2304;
        src = Wi + (size_t)l * DD * FFD;
        dh = g_WiT_h + (size_t)l * DD * FFD; dl = g_WiT_l + (size_t)l * DD * FFD;
        K = DD; N = FFD; rowoff = 0; ky = q2 / 96; nx = q2 % 96;
    } else {
        int q2 = r - 4608;
        src = Wf + (size_t)l * FFD * DD;
        dh = g_WfT_h + (size_t)l * DD * FFD; dl = g_WfT_l + (size_t)l * DD * FFD;
        K = FFD; N = DD; rowoff = 0; ky = q2 / 24; nx = q2 % 24;
    }
    int n0 = nx * 32, k0 = ky * 32;
    int tx = threadIdx.x;
    for (int i = threadIdx.y; i < 32; i += 8)
        tsm[i][tx] = src[(size_t)(k0 + i) * N + n0 + tx];
    __syncthreads();
    for (int i = threadIdx.y; i < 32; i += 8) {
        float v = tsm[tx][i];
        __nv_bfloat16 hi, lo; split_bf16(v, hi, lo);
        size_t o = (size_t)(rowoff + n0 + i) * K + k0 + tx;
        dh[o] = hi; dl[o] = lo;
    }
}

__global__ void fuse_bias(const float* __restrict__ bq, const float* __restrict__ bk,
                          const float* __restrict__ bv)
{
    int i = blockIdx.x * 256 + threadIdx.x;
    if (i >= LL * NQKV) return;
    int l = i / NQKV, n = i % NQKV;
    g_bqkv[i] = (n < DD) ? bq[l * DD + n]
              : (n < 2 * DD) ? bk[l * DD + n - DD]
                             : bv[l * DD + n - 2 * DD];
}

// ---------------- embedding / layernorm ------------------------------------------
__global__ void embed_ln_kernel(const int* __restrict__ ids, const float* __restrict__ we,
                                const float* __restrict__ pe, const float* __restrict__ te,
                                const float* __restrict__ gam, const float* __restrict__ bet,
                                float* __restrict__ out,
                                __nv_bfloat16* __restrict__ oh, __nv_bfloat16* __restrict__ ol)
{
    __shared__ float xs[DD];
    __shared__ float red[32];
    int tok = blockIdx.x, s = tok & (SS - 1), id = ids[tok], tid = threadIdx.x;
    const float* wrow = we + (size_t)id * DD;
    const float* prow = pe + (size_t)s * DD;
    float sum = 0.f;
    for (int d = tid; d < DD; d += 256) {
        float v = wrow[d] + prow[d] + te[d];
        xs[d] = v; sum += v;
    }
    float mu = blockReduceSum(sum, red) * (1.0f / DD);
    float vs = 0.f;
    for (int d = tid; d < DD; d += 256) { float dl = xs[d] - mu; vs += dl * dl; }
    float var = blockReduceSum(vs, red) * (1.0f / DD);
    float r = rsqrtf(var + 1e-12f);
    size_t ro = (size_t)tok * DD;
    for (int d = tid; d < DD; d += 256) {
        float o = (xs[d] - mu) * r * gam[d] + bet[d];
        out[ro + d] = o;
        __nv_bfloat16 hi, lo; split_bf16(o, hi, lo);
        oh[ro + d] = hi; ol[ro + d] = lo;
    }
}

__global__ void layernorm_kernel(const float* __restrict__ x, const float* __restrict__ gam,
                                 const float* __restrict__ bet, float* __restrict__ out,
                                 __nv_bfloat16* __restrict__ oh, __nv_bfloat16* __restrict__ ol)
{
    __shared__ float xs[DD];
    __shared__ float red[32];
    int row = blockIdx.x, tid = threadIdx.x;
    const float* xr = x + (size_t)row * DD;
    float sum = 0.f;
    for (int d = tid; d < DD; d += 256) { float v = xr[d]; xs[d] = v; sum += v; }
    float mu = blockReduceSum(sum, red) * (1.0f / DD);
    float vs = 0.f;
    for (int d = tid; d < DD; d += 256) { float dl = xs[d] - mu; vs += dl * dl; }
    float var = blockReduceSum(vs, red) * (1.0f / DD);
    float r = rsqrtf(var + 1e-12f);
    size_t ro = (size_t)row * DD;
    for (int d = tid; d < DD; d += 256) {
        float o = (xs[d] - mu) * r * gam[d] + bet[d];
        out[ro + d] = o;
        __nv_bfloat16 hi, lo; split_bf16(o, hi, lo);
        oh[ro + d] = hi; ol[ro + d] = lo;
    }
}

// ---------------- GEMM: 3-stage cp.async, 2 CTA/SM -------------------------------
// mode 1: +bias,GELU -> Ch/Cl bf16 ; mode 2: +bias+res -> C fp32 ; mode 3: QKV -> Ch/Cl
#define GSTG 3
#define GEMM_SMEM (GSTG*32768 + 1024)

__global__ __launch_bounds__(256, 2)
void gemm_mma(const __nv_bfloat16* __restrict__ Ah, const __nv_bfloat16* __restrict__ Al,
              const __nv_bfloat16* __restrict__ Bh, const __nv_bfloat16* __restrict__ Bl,
              const float* __restrict__ bias, const float* __restrict__ res,
              float* __restrict__ C,
              __nv_bfloat16* __restrict__ Ch, __nv_bfloat16* __restrict__ Cl,
              int M, int N, int K, int mode)
{
    extern __shared__ char dsm[];
    uint32_t raw = smem_u32(dsm);
    uint32_t s0 = (raw + 1023) & ~1023u;

    int tid = threadIdx.x, wid = tid >> 5, lane = tid & 31;
    int wm = wid & 1, wn = wid >> 1;
    long mBase = (long)blockIdx.y * 128;
    long nBase = (long)blockIdx.x * 128;

    float acc[4][4][4];
    #pragma unroll
    for (int i = 0; i < 4; i++)
        #pragma unroll
        for (int j = 0; j < 4; j++)
            #pragma unroll
            for (int q = 0; q < 4; q++) acc[i][j][q] = 0.f;

    int lrow = tid >> 1, lkc0 = (tid & 1) * 2;
    const __nv_bfloat16* Ahp = Ah + (size_t)(mBase + lrow) * K;
    const __nv_bfloat16* Alp = Al + (size_t)(mBase + lrow) * K;
    const __nv_bfloat16* Bhp = Bh + (size_t)(nBase + lrow) * K;
    const __nv_bfloat16* Blp = Bl + (size_t)(nBase + lrow) * K;
    uint32_t sw0 = swz(lrow * 64 + lkc0 * 16);
    uint32_t sw1 = swz(lrow * 64 + (lkc0 + 1) * 16);
    const int nIt = K / 32;

    #pragma unroll 1
    for (int pf = 0; pf < 2; pf++) {
        uint32_t sb = s0 + pf * 32768;
        int k0 = pf * 32 + lkc0 * 8;
        cpa16(sb + sw0, Ahp + k0);          cpa16(sb + sw1, Ahp + k0 + 8);
        cpa16(sb + 8192 + sw0, Alp + k0);   cpa16(sb + 8192 + sw1, Alp + k0 + 8);
        cpa16(sb + 16384 + sw0, Bhp + k0);  cpa16(sb + 16384 + sw1, Bhp + k0 + 8);
        cpa16(sb + 24576 + sw0, Blp + k0);  cpa16(sb + 24576 + sw1, Blp + k0 + 8);
        cp_commit();
    }

    #pragma unroll 1
    for (int it = 0; it < nIt; ++it) {
        if (it < nIt - 1) cp_wait<1>(); else cp_wait<0>();
        __syncthreads();
        if (it + 2 < nIt) {
            uint32_t sb = s0 + ((it + 2) % GSTG) * 32768;
            int k0 = (it + 2) * 32 + lkc0 * 8;
            cpa16(sb + sw0, Ahp + k0);          cpa16(sb + sw1, Ahp + k0 + 8);
            cpa16(sb + 8192 + sw0, Alp + k0);   cpa16(sb + 8192 + sw1, Alp + k0 + 8);
            cpa16(sb + 16384 + sw0, Bhp + k0);  cpa16(sb + 16384 + sw1, Bhp + k0 + 8);
            cpa16(sb + 24576 + sw0, Blp + k0);  cpa16(sb + 24576 + sw1, Blp + k0 + 8);
            cp_commit();
        }
        uint32_t base = s0 + (it % GSTG) * 32768;
        #pragma unroll
        for (int ks = 0; ks < 2; ks++) {
            uint32_t kcol = (ks * 2 + (lane >> 4)) * 16;
            int brow = wn * 32 + (lane & 15);
            uint32_t bh[4][2], bl[4][2];
            #pragma unroll
            for (int n2 = 0; n2 < 2; n2++) {
                uint32_t r0, r1, r2, r3;
                ldsm4(r0, r1, r2, r3, base + 16384 + swz((brow + n2 * 16) * 64 + kcol));
                bh[n2*2][0] = r0; bh[n2*2][1] = r2; bh[n2*2+1][0] = r1; bh[n2*2+1][1] = r3;
                ldsm4(r0, r1, r2, r3, base + 24576 + swz((brow + n2 * 16) * 64 + kcol));
                bl[n2*2][0] = r0; bl[n2*2][1] = r2; bl[n2*2+1][0] = r1; bl[n2*2+1][1] = r3;
            }
            int arow = wm * 64 + (lane & 15);
            #pragma unroll
            for (int mt = 0; mt < 4; mt++) {
                uint32_t a[4];
                ldsm4(a[0], a[1], a[2], a[3], base + swz((arow + mt * 16) * 64 + kcol));
                #pragma unroll
                for (int nt = 0; nt < 4; nt++) mma_bf16(acc[mt][nt], a, bh[nt]);
                #pragma unroll
                for (int nt = 0; nt < 4; nt++) mma_bf16(acc[mt][nt], a, bl[nt]);
                ldsm4(a[0], a[1], a[2], a[3], base + 8192 + swz((arow + mt * 16) * 64 + kcol));
                #pragma unroll
                for (int nt = 0; nt < 4; nt++) mma_bf16(acc[mt][nt], a, bh[nt]);
            }
        }
    }

    #pragma unroll
    for (int mt = 0; mt < 4; mt++) {
        #pragma unroll
        for (int half = 0; half < 2; half++) {
            long m = mBase + wm * 64 + mt * 16 + (lane >> 2) + half * 8;
            #pragma unroll
            for (int nt = 0; nt < 4; nt++) {
                long n0 = nBase + wn * 32 + nt * 8 + (lane & 3) * 2;
                float v0 = acc[mt][nt][half * 2] + __ldg(bias + n0);
                float v1 = acc[mt][nt][half * 2 + 1] + __ldg(bias + n0 + 1);
                if (mode == 2) {
                    float2 rv = *(const float2*)(res + m * N + n0);
                    v0 += rv.x; v1 += rv.y;
                    *(float2*)(C + m * N + n0) = make_float2(v0, v1);
                } else if (mode == 1) {
                    v0 = 0.5f * v0 * (1.0f + erff(v0 * 0.70710678118654752f));
                    v1 = 0.5f * v1 * (1.0f + erff(v1 * 0.70710678118654752f));
                    uint32_t ph, pl; pack2(v0, v1, ph, pl);
                    *(uint32_t*)(Ch + m * N + n0) = ph;
                    *(uint32_t*)(Cl + m * N + n0) = pl;
                } else { // mode 3 (QKV): Q columns scaled by 1/8
                    float sc = (n0 < DD) ? 0.125f : 1.0f;
                    uint32_t ph, pl; pack2(v0 * sc, v1 * sc, ph, pl);
                    *(uint32_t*)(Ch + m * N + n0) = ph;
                    *(uint32_t*)(Cl + m * N + n0) = pl;
                }
            }
        }
    }
}

// ---------------- flash attention (bf16 in, cp.async 3-stage KV) -----------------
#define A_QH 0
#define A_QL 16384
#define A_KV 32768              // stage s: base + s*32768 : KH,KL,VH,VL (8KB each)
#define A_MK (32768 + 98304)    // 131072
#define ATTN_SMEM (131072 + 2048 + 1024)

__global__ __launch_bounds__(256, 1)
void attn_flash(const __nv_bfloat16* __restrict__ qkv_h,
                const __nv_bfloat16* __restrict__ qkv_l,
                const int* __restrict__ mask,
                __nv_bfloat16* __restrict__ ctx_h, __nv_bfloat16* __restrict__ ctx_l)
{
    extern __shared__ char dsm[];
    uint32_t raw = smem_u32(dsm);
    uint32_t s0 = (raw + 1023) & ~1023u;
    char* sm = dsm + (s0 - raw);

    int b = blockIdx.z, h = blockIdx.y, qt = blockIdx.x;
    int tid = threadIdx.x, wid = tid >> 5, lane = tid & 31;
    int q0 = b * SS + qt * 128;
    int k0g = b * SS;

    float* maskf = (float*)(sm + A_MK);
    for (int i = tid; i < SS; i += 256) maskf[i] = (float)mask[b * SS + i];

    // Q via cp.async (group 0)
    #pragma unroll
    for (int r2 = 0; r2 < 4; r2++) {
        int i = tid + r2 * 256;
        int row = i >> 3, c = i & 7;
        uint32_t sw = swz(row * 128 + c * 16);
        size_t gq = (size_t)(q0 + row) * NQKV + h * DH + c * 8;
        cpa16(s0 + A_QH + sw, qkv_h + gq);
        cpa16(s0 + A_QL + sw, qkv_l + gq);
    }
    cp_commit();

    auto ldKV = [&](int ch, int stg) {
        uint32_t kb = s0 + A_KV + stg * 32768;
        #pragma unroll
        for (int r2 = 0; r2 < 2; r2++) {
            int i = tid + r2 * 256;
            int row = i >> 3, c = i & 7;
            uint32_t sw = swz(row * 128 + c * 16);
            size_t gk = (size_t)(k0g + ch * 64 + row) * NQKV + DD + h * DH + c * 8;
            cpa16(kb + sw,         qkv_h + gk);
            cpa16(kb + 8192 + sw,  qkv_l + gk);
            cpa16(kb + 16384 + sw, qkv_h + gk + DD);
            cpa16(kb + 24576 + sw, qkv_l + gk + DD);
        }
        cp_commit();
    };
    ldKV(0, 0);
    ldKV(1, 1);

    cp_wait<2>(); __syncthreads();   // Q + mask ready

    uint32_t qh[4][4], ql[4][4];
    {
        int qr = wid * 16 + (lane & 15);
        #pragma unroll
        for (int ks = 0; ks < 4; ks++) {
            uint32_t o2 = swz(qr * 128 + (ks * 2 + (lane >> 4)) * 16);
            ldsm4(qh[ks][0], qh[ks][1], qh[ks][2], qh[ks][3], s0 + A_QH + o2);
            ldsm4(ql[ks][0], ql[ks][1], ql[ks][2], ql[ks][3], s0 + A_QL + o2);
        }
    }

    float M[2] = {-1e30f, -1e30f}, Zs[2] = {0.f, 0.f}, Zm[2] = {0.f, 0.f};
    float o[8][4];
    #pragma unroll
    for (int i = 0; i < 8; i++)
        #pragma unroll
        for (int j = 0; j < 4; j++) o[i][j] = 0.f;

    #pragma unroll 1
    for (int ch = 0; ch < 8; ch++) {
        if (ch < 7) cp_wait<1>(); else cp_wait<0>();
        __syncthreads();
        if (ch + 2 < 8) ldKV(ch + 2, (ch + 2) % 3);

        uint32_t kb = s0 + A_KV + (ch % 3) * 32768;
        float s[8][4];
        #pragma unroll
        for (int i = 0; i < 8; i++)
            #pragma unroll
            for (int j = 0; j < 4; j++) s[i][j] = 0.f;

        #pragma unroll
        for (int n4 = 0; n4 < 4; n4++) {
            int br = n4 * 16 + (lane & 15);
            #pragma unroll
            for (int ks = 0; ks < 4; ks++) {
                uint32_t kcol = (ks * 2 + (lane >> 4)) * 16;
                uint32_t r0, r1, r2, r3;
                uint32_t bh0[2], bh1[2], bl0[2], bl1[2];
                ldsm4(r0, r1, r2, r3, kb + swz(br * 128 + kcol));
                bh0[0] = r0; bh0[1] = r2; bh1[0] = r1; bh1[1] = r3;
                ldsm4(r0, r1, r2, r3, kb + 8192 + swz(br * 128 + kcol));
                bl0[0] = r0; bl0[1] = r2; bl1[0] = r1; bl1[1] = r3;
                mma_bf16(s[n4*2], qh[ks], bh0);  mma_bf16(s[n4*2+1], qh[ks], bh1);
                mma_bf16(s[n4*2], qh[ks], bl0);  mma_bf16(s[n4*2+1], qh[ks], bl1);
                mma_bf16(s[n4*2], ql[ks], bh0);  mma_bf16(s[n4*2+1], ql[ks], bh1);
            }
        }

        #pragma unroll
        for (int g = 0; g < 2; g++) {
            float mx = -1e30f;
            #pragma unroll
            for (int nt = 0; nt < 8; nt++)
                mx = fmaxf(mx, fmaxf(s[nt][2*g], s[nt][2*g+1]));
            mx = fmaxf(mx, __shfl_xor_sync(0xffffffffu, mx, 1));
            mx = fmaxf(mx, __shfl_xor_sync(0xffffffffu, mx, 2));
            float Mn = fmaxf(M[g], mx);
            float fac = __expf(M[g] - Mn);
            float zc = 0.f, zmc = 0.f;
            #pragma unroll
            for (int nt = 0; nt < 8; nt++) {
                #pragma unroll
                for (int e = 0; e < 2; e++) {
                    int col = ch * 64 + nt * 8 + (lane & 3) * 2 + e;
                    float ex = __expf(s[nt][2*g+e] - Mn);
                    float mm = maskf[col];
                    zc += ex; zmc += ex * mm;
                    s[nt][2*g+e] = ex * mm;
                }
            }
            zc += __shfl_xor_sync(0xffffffffu, zc, 1);
            zc += __shfl_xor_sync(0xffffffffu, zc, 2);
            zmc += __shfl_xor_sync(0xffffffffu, zmc, 1);
            zmc += __shfl_xor_sync(0xffffffffu, zmc, 2);
            Zs[g] = Zs[g] * fac + zc;
            Zm[g] = Zm[g] * fac + zmc;
            M[g] = Mn;
            #pragma unroll
            for (int nt = 0; nt < 8; nt++) { o[nt][2*g] *= fac; o[nt][2*g+1] *= fac; }
        }

        uint32_t ah[4][4], al[4][4];
        #pragma unroll
        for (int kt = 0; kt < 4; kt++) {
            pack2(s[2*kt][0],   s[2*kt][1],   ah[kt][0], al[kt][0]);
            pack2(s[2*kt][2],   s[2*kt][3],   ah[kt][1], al[kt][1]);
            pack2(s[2*kt+1][0], s[2*kt+1][1], ah[kt][2], al[kt][2]);
            pack2(s[2*kt+1][2], s[2*kt+1][3], ah[kt][3], al[kt][3]);
        }

        uint32_t vb = kb + 16384;
        #pragma unroll
        for (int n4 = 0; n4 < 4; n4++) {
            #pragma unroll
            for (int kt = 0; kt < 4; kt++) {
                uint32_t addr = swz((kt * 16 + (lane & 15)) * 128 + n4 * 32 + (lane >> 4) * 16);
                uint32_t r0, r1, r2, r3;
                uint32_t bh0[2], bh1[2], bl0[2], bl1[2];
                ldsm4t(r0, r1, r2, r3, vb + addr);
                bh0[0] = r0; bh0[1] = r1; bh1[0] = r2; bh1[1] = r3;
                ldsm4t(r0, r1, r2, r3, vb + 8192 + addr);
                bl0[0] = r0; bl0[1] = r1; bl1[0] = r2; bl1[1] = r3;
                mma_bf16(o[n4*2], ah[kt], bh0);  mma_bf16(o[n4*2+1], ah[kt], bh1);
                mma_bf16(o[n4*2], ah[kt], bl0);  mma_bf16(o[n4*2+1], ah[kt], bl1);
                mma_bf16(o[n4*2], al[kt], bh0);  mma_bf16(o[n4*2+1], al[kt], bh1);
            }
        }
    }

    #pragma unroll
    for (int g = 0; g < 2; g++) {
        float den = fmaxf(Zm[g], 1e-9f * Zs[g]);
        float rcp = 1.0f / den;
        size_t row = q0 + wid * 16 + (lane >> 2) + g * 8;
        #pragma unroll
        for (int nt = 0; nt < 8; nt++) {
            int col = h * DH + nt * 8 + (lane & 3) * 2;
            uint32_t ph, pl;
            pack2(o[nt][2*g] * rcp, o[nt][2*g+1] * rcp, ph, pl);
            *(uint32_t*)(ctx_h + row * DD + col) = ph;
            *(uint32_t*)(ctx_l + row * DD + col) = pl;
        }
    }
}

// ---------------- pool + normalize ------------------------------------------------
__global__ void pool_kernel(const float* __restrict__ h, const int* __restrict__ mask,
                            float* __restrict__ out)
{
    __shared__ float sent[DD];
    __shared__ float red[32];
    int b = blockIdx.x, tid = threadIdx.x;
    float ms = 0.f;
    for (int s = tid; s < SS; s += 256) ms += (float)mask[b * SS + s];
    ms = blockReduceSum(ms, red);
    float inv = 1.0f / fmaxf(ms, 1e-6f);
    for (int d = tid; d < DD; d += 256) {
        float a = 0.f;
        const float* hp = h + ((size_t)b * SS) * DD + d;
        const int* mp = mask + b * SS;
        for (int s = 0; s < SS; s++) a += hp[(size_t)s * DD] * (float)mp[s];
        sent[d] = a * inv;
    }
    __syncthreads();
    float sq = 0.f;
    for (int d = tid; d < DD; d += 256) sq += sent[d] * sent[d];
    sq = blockReduceSum(sq, red);
    float rn = 1.0f / fmaxf(sqrtf(sq), 1e-12f);
    for (int d = tid; d < DD; d += 256) out[b * DD + d] = sent[d] * rn;
}

// ---------------- launch -----------------------------------------------------------
extern "C" void kernel_launch(void* const* d_in, const int* in_sizes, int n_in,
                              void* d_out, int out_size)
{
    const int*   input_ids = (const int*)  d_in[0];
    const int*   amask     = (const int*)  d_in[1];
    const float* word_emb  = (const float*)d_in[2];
    const float* pos_emb   = (const float*)d_in[3];
    const float* type_emb  = (const float*)d_in[4];
    const float* emb_g     = (const float*)d_in[5];
    const float* emb_b     = (const float*)d_in[6];
    const float* Wq = (const float*)d_in[7];  const float* bq = (const float*)d_in[8];
    const float* Wk = (const float*)d_in[9];  const float* bk = (const float*)d_in[10];
    const float* Wv = (const float*)d_in[11]; const float* bv = (const float*)d_in[12];
    const float* Wo = (const float*)d_in[13]; const float* bo = (const float*)d_in[14];
    const float* ln1g = (const float*)d_in[15]; const float* ln1b = (const float*)d_in[16];
    const float* Wi = (const float*)d_in[17]; const float* bi = (const float*)d_in[18];
    const float* Wf = (const float*)d_in[19]; const float* bf = (const float*)d_in[20];
    const float* ln2g = (const float*)d_in[21]; const float* ln2b = (const float*)d_in[22];
    float* out = (float*)d_out;

    float *p_h, *p_t1, *p_bqkv;
    __nv_bfloat16 *p_hh, *p_hl, *p_qh, *p_ql, *p_ch, *p_cl, *p_fh, *p_fl;
    __nv_bfloat16 *wqkv_h, *wqkv_l, *wo_h, *wo_l, *wi_h, *wi_l, *wf_h, *wf_l;
    cudaGetSymbolAddress((void**)&p_h,  g_h);
    cudaGetSymbolAddress((void**)&p_t1, g_t1);
    cudaGetSymbolAddress((void**)&p_bqkv, g_bqkv);
    cudaGetSymbolAddress((void**)&p_hh, g_h_hi);
    cudaGetSymbolAddress((void**)&p_hl, g_h_lo);
    cudaGetSymbolAddress((void**)&p_qh, g_qkv_h);
    cudaGetSymbolAddress((void**)&p_ql, g_qkv_l);
    cudaGetSymbolAddress((void**)&p_ch, g_ctx_hi);
    cudaGetSymbolAddress((void**)&p_cl, g_ctx_lo);
    cudaGetSymbolAddress((void**)&p_fh, g_ff_hi);
    cudaGetSymbolAddress((void**)&p_fl, g_ff_lo);
    cudaGetSymbolAddress((void**)&wqkv_h, g_Wqkv_h); cudaGetSymbolAddress((void**)&wqkv_l, g_Wqkv_l);
    cudaGetSymbolAddress((void**)&wo_h, g_WoT_h);    cudaGetSymbolAddress((void**)&wo_l, g_WoT_l);
    cudaGetSymbolAddress((void**)&wi_h, g_WiT_h);    cudaGetSymbolAddress((void**)&wi_l, g_WiT_l);
    cudaGetSymbolAddress((void**)&wf_h, g_WfT_h);    cudaGetSymbolAddress((void**)&wf_l, g_WfT_l);

    cudaFuncSetAttribute(gemm_mma, cudaFuncAttributeMaxDynamicSharedMemorySize, GEMM_SMEM);
    cudaFuncSetAttribute(attn_flash, cudaFuncAttributeMaxDynamicSharedMemorySize, ATTN_SMEM);

    trans_all<<<LL * 6912, dim3(32, 8)>>>(Wq, Wk, Wv, Wo, Wi, Wf);
    fuse_bias<<<(LL * NQKV + 255) / 256, 256>>>(bq, bk, bv);
    embed_ln_kernel<<<MTOK, 256>>>(input_ids, word_emb, pos_emb, type_emb,
                                   emb_g, emb_b, p_h, p_hh, p_hl);

    dim3 gQKV(NQKV / 128, MTOK / 128);
    dim3 gD  (DD   / 128, MTOK / 128);
    dim3 gFF (FFD  / 128, MTOK / 128);

    for (int l = 0; l < LL; l++) {
        size_t wdd = (size_t)l * DD * DD;
        size_t wdf = (size_t)l * DD * FFD;
        size_t wqk = (size_t)l * NQKV * DD;

        gemm_mma<<<gQKV, 256, GEMM_SMEM>>>(p_hh, p_hl, wqkv_h + wqk, wqkv_l + wqk,
                                           p_bqkv + l * NQKV, nullptr, nullptr,
                                           p_qh, p_ql, MTOK, NQKV, DD, 3);

        attn_flash<<<dim3(4, HH, BB), 256, ATTN_SMEM>>>(p_qh, p_ql, amask, p_ch, p_cl);

        gemm_mma<<<gD, 256, GEMM_SMEM>>>(p_ch, p_cl, wo_h + wdd, wo_l + wdd,
                                         bo + l * DD, p_h, p_t1, nullptr, nullptr,
                                         MTOK, DD, DD, 2);
        layernorm_kernel<<<MTOK, 256>>>(p_t1, ln1g + l * DD, ln1b + l * DD,
                                        p_h, p_hh, p_hl);

        gemm_mma<<<gFF, 256, GEMM_SMEM>>>(p_hh, p_hl, wi_h + wdf, wi_l + wdf,
                                          bi + l * FFD, nullptr, nullptr, p_fh, p_fl,
                                          MTOK, FFD, DD, 1);
        gemm_mma<<<gD, 256, GEMM_SMEM>>>(p_fh, p_fl, wf_h + wdf, wf_l + wdf,
                                         bf + l * DD, p_h, p_t1, nullptr, nullptr,
                                         MTOK, DD, FFD, 2);
        layernorm_kernel<<<MTOK, 256>>>(p_t1, ln2g + l * DD, ln2b + l * DD,
                                        p_h, p_hh, p_hl);
    }

    pool_kernel<<<BB, 256>>>(p_h, amask, out);
}

// round 7
// speedup vs baseline: 2.7134x; 1.1437x over previous
#include <cuda_runtime.h>
#include <cuda_bf16.h>
#include <math.h>
#include <stdint.h>

#define BB 8
#define SS 512
#define DD 768
#define HH 12
#define DH 64
#define LL 12
#define FFD 3072
#define MTOK (BB*SS)
#define NQKV 2304

__device__ __align__(256) float g_h  [MTOK*DD];
__device__ __align__(256) float g_t1 [MTOK*DD];
__device__ __align__(256) float g_t2 [MTOK*DD];

__device__ __align__(256) __nv_bfloat16 g_h_hi [MTOK*DD];
__device__ __align__(256) __nv_bfloat16 g_h_lo [MTOK*DD];
__device__ __align__(256) __nv_bfloat16 g_qkv_h[MTOK*NQKV];
__device__ __align__(256) __nv_bfloat16 g_qkv_l[MTOK*NQKV];
__device__ __align__(256) __nv_bfloat16 g_ctx_hi[MTOK*DD];
__device__ __align__(256) __nv_bfloat16 g_ctx_lo[MTOK*DD];
__device__ __align__(256) __nv_bfloat16 g_ff_hi[MTOK*FFD];
__device__ __align__(256) __nv_bfloat16 g_ff_lo[MTOK*FFD];

__device__ __align__(256) __nv_bfloat16 g_Wqkv_h[LL*NQKV*DD];
__device__ __align__(256) __nv_bfloat16 g_Wqkv_l[LL*NQKV*DD];
__device__ __align__(256) __nv_bfloat16 g_WoT_h[LL*DD*DD];
__device__ __align__(256) __nv_bfloat16 g_WoT_l[LL*DD*DD];
__device__ __align__(256) __nv_bfloat16 g_WiT_h[LL*DD*FFD];
__device__ __align__(256) __nv_bfloat16 g_WiT_l[LL*DD*FFD];
__device__ __align__(256) __nv_bfloat16 g_WfT_h[LL*DD*FFD];
__device__ __align__(256) __nv_bfloat16 g_WfT_l[LL*DD*FFD];
__device__ __align__(256) float g_bqkv[LL*NQKV];

// ---------------- helpers ------------------------------------------------------
__device__ __forceinline__ uint32_t smem_u32(const void* p) {
    uint32_t a;
    asm("{ .reg .u64 t; cvta.to.shared.u64 t, %1; cvt.u32.u64 %0, t; }" : "=r"(a) : "l"(p));
    return a;
}
__device__ __forceinline__ uint32_t swz(uint32_t o) { return o ^ ((o >> 3) & 0x70); }
__device__ __forceinline__ void cpa16(uint32_t saddr, const void* g) {
    asm volatile("cp.async.cg.shared.global [%0], [%1], 16;" :: "r"(saddr), "l"(g));
}
__device__ __forceinline__ void cp_commit() {
    asm volatile("cp.async.commit_group;" ::: "memory");
}
template <int N>
__device__ __forceinline__ void cp_wait() {
    asm volatile("cp.async.wait_group %0;" :: "n"(N) : "memory");
}
__device__ __forceinline__ void ldsm4(uint32_t& r0, uint32_t& r1, uint32_t& r2, uint32_t& r3,
                                      uint32_t addr) {
    asm volatile("ldmatrix.sync.aligned.m8n8.x4.shared.b16 {%0,%1,%2,%3}, [%4];"
                 : "=r"(r0), "=r"(r1), "=r"(r2), "=r"(r3) : "r"(addr));
}
__device__ __forceinline__ void ldsm4t(uint32_t& r0, uint32_t& r1, uint32_t& r2, uint32_t& r3,
                                       uint32_t addr) {
    asm volatile("ldmatrix.sync.aligned.m8n8.x4.trans.shared.b16 {%0,%1,%2,%3}, [%4];"
                 : "=r"(r0), "=r"(r1), "=r"(r2), "=r"(r3) : "r"(addr));
}
__device__ __forceinline__ void mma_bf16(float* d, const uint32_t* a, const uint32_t* b) {
    asm volatile("mma.sync.aligned.m16n8k16.row.col.f32.bf16.bf16.f32 "
                 "{%0,%1,%2,%3}, {%4,%5,%6,%7}, {%8,%9}, {%0,%1,%2,%3};"
                 : "+f"(d[0]), "+f"(d[1]), "+f"(d[2]), "+f"(d[3])
                 : "r"(a[0]), "r"(a[1]), "r"(a[2]), "r"(a[3]), "r"(b[0]), "r"(b[1]));
}
__device__ __forceinline__ void split_bf16(float x, __nv_bfloat16& hi, __nv_bfloat16& lo) {
    hi = __float2bfloat16(x);
    lo = __float2bfloat16(x - __bfloat162float(hi));
}
__device__ __forceinline__ void pack2(float a, float b, uint32_t& ph, uint32_t& pl) {
    __nv_bfloat16 ha, la, hb, lb;
    split_bf16(a, ha, la); split_bf16(b, hb, lb);
    __nv_bfloat162 th(ha, hb), tl(la, lb);
    ph = *(uint32_t*)&th; pl = *(uint32_t*)&tl;
}
__device__ __forceinline__ float blockReduceSum(float v, float* red) {
    int lane = threadIdx.x & 31, w = threadIdx.x >> 5;
    #pragma unroll
    for (int o = 16; o; o >>= 1) v += __shfl_xor_sync(0xffffffffu, v, o);
    if (lane == 0) red[w] = v;
    __syncthreads();
    float t = (threadIdx.x < (blockDim.x >> 5)) ? red[threadIdx.x] : 0.f;
    if (w == 0) {
        #pragma unroll
        for (int o = 16; o; o >>= 1) t += __shfl_xor_sync(0xffffffffu, t, o);
        if (lane == 0) red[0] = t;
    }
    __syncthreads();
    return red[0];
}

// ---------------- weight prep ------------------------------------------------------
__global__ void trans_all(const float* __restrict__ Wq, const float* __restrict__ Wk,
                          const float* __restrict__ Wv, const float* __restrict__ Wo,
                          const float* __restrict__ Wi, const float* __restrict__ Wf)
{
    __shared__ float tsm[32][33];
    int t = blockIdx.x;
    int l = t / 6912, r = t % 6912;
    const float* src; __nv_bfloat16 *dh, *dl;
    int K, N, rowoff, nx, ky;
    if (r < 1728) {
        int w = r / 576, q2 = r % 576;
        src = (w == 0 ? Wq : w == 1 ? Wk : Wv) + (size_t)l * DD * DD;
        dh = g_Wqkv_h + (size_t)l * NQKV * DD; dl = g_Wqkv_l + (size_t)l * NQKV * DD;
        K = DD; N = DD; rowoff = w * DD; ky = q2 / 24; nx = q2 % 24;
    } else if (r < 2304) {
        int q2 = r - 1728;
        src = Wo + (size_t)l * DD * DD;
        dh = g_WoT_h + (size_t)l * DD * DD; dl = g_WoT_l + (size_t)l * DD * DD;
        K = DD; N = DD; rowoff = 0; ky = q2 / 24; nx = q2 % 24;
    } else if (r < 4608) {
        int q2 = r - 2304;
        src = Wi + (size_t)l * DD * FFD;
        dh = g_WiT_h + (size_t)l * DD * FFD; dl = g_WiT_l + (size_t)l * DD * FFD;
        K = DD; N = FFD; rowoff = 0; ky = q2 / 96; nx = q2 % 96;
    } else {
        int q2 = r - 4608;
        src = Wf + (size_t)l * FFD * DD;
        dh = g_WfT_h + (size_t)l * DD * FFD; dl = g_WfT_l + (size_t)l * DD * FFD;
        K = FFD; N = DD; rowoff = 0; ky = q2 / 24; nx = q2 % 24;
    }
    int n0 = nx * 32, k0 = ky * 32;
    int tx = threadIdx.x;
    for (int i = threadIdx.y; i < 32; i += 8)
        tsm[i][tx] = src[(size_t)(k0 + i) * N + n0 + tx];
    __syncthreads();
    for (int i = threadIdx.y; i < 32; i += 8) {
        float v = tsm[tx][i];
        __nv_bfloat16 hi, lo; split_bf16(v, hi, lo);
        size_t o = (size_t)(rowoff + n0 + i) * K + k0 + tx;
        dh[o] = hi; dl[o] = lo;
    }
}

__global__ void fuse_bias(const float* __restrict__ bq, const float* __restrict__ bk,
                          const float* __restrict__ bv)
{
    int i = blockIdx.x * 256 + threadIdx.x;
    if (i >= LL * NQKV) return;
    int l = i / NQKV, n = i % NQKV;
    g_bqkv[i] = (n < DD) ? bq[l * DD + n]
              : (n < 2 * DD) ? bk[l * DD + n - DD]
                             : bv[l * DD + n - 2 * DD];
}

// ---------------- embedding LN -------------------------------------------------
__global__ void embed_ln_kernel(const int* __restrict__ ids, const float* __restrict__ we,
                                const float* __restrict__ pe, const float* __restrict__ te,
                                const float* __restrict__ gam, const float* __restrict__ bet,
                                float* __restrict__ out,
                                __nv_bfloat16* __restrict__ oh, __nv_bfloat16* __restrict__ ol)
{
    __shared__ float xs[DD];
    __shared__ float red[32];
    int tok = blockIdx.x, s = tok & (SS - 1), id = ids[tok], tid = threadIdx.x;
    const float* wrow = we + (size_t)id * DD;
    const float* prow = pe + (size_t)s * DD;
    float sum = 0.f;
    for (int d = tid; d < DD; d += 256) {
        float v = wrow[d] + prow[d] + te[d];
        xs[d] = v; sum += v;
    }
    float mu = blockReduceSum(sum, red) * (1.0f / DD);
    float vs = 0.f;
    for (int d = tid; d < DD; d += 256) { float dl = xs[d] - mu; vs += dl * dl; }
    float var = blockReduceSum(vs, red) * (1.0f / DD);
    float r = rsqrtf(var + 1e-12f);
    size_t ro = (size_t)tok * DD;
    for (int d = tid; d < DD; d += 256) {
        float o = (xs[d] - mu) * r * gam[d] + bet[d];
        out[ro + d] = o;
        __nv_bfloat16 hi, lo; split_bf16(o, hi, lo);
        oh[ro + d] = hi; ol[ro + d] = lo;
    }
}

// LN over (p0 + p1 + bias + res); writes fp32 + bf16 hi/lo
__global__ void ln_sum_kernel(const float* __restrict__ p0, const float* __restrict__ p1,
                              const float* __restrict__ bias, const float* __restrict__ res,
                              const float* __restrict__ gam, const float* __restrict__ bet,
                              float* __restrict__ out,
                              __nv_bfloat16* __restrict__ oh, __nv_bfloat16* __restrict__ ol)
{
    __shared__ float xs[DD];
    __shared__ float red[32];
    int row = blockIdx.x, tid = threadIdx.x;
    size_t ro = (size_t)row * DD;
    float sum = 0.f;
    for (int d = tid; d < DD; d += 256) {
        float v = p0[ro + d] + p1[ro + d] + bias[d] + res[ro + d];
        xs[d] = v; sum += v;
    }
    float mu = blockReduceSum(sum, red) * (1.0f / DD);
    float vs = 0.f;
    for (int d = tid; d < DD; d += 256) { float dl = xs[d] - mu; vs += dl * dl; }
    float var = blockReduceSum(vs, red) * (1.0f / DD);
    float r = rsqrtf(var + 1e-12f);
    for (int d = tid; d < DD; d += 256) {
        float o = (xs[d] - mu) * r * gam[d] + bet[d];
        out[ro + d] = o;
        __nv_bfloat16 hi, lo; split_bf16(o, hi, lo);
        oh[ro + d] = hi; ol[ro + d] = lo;
    }
}

// ---------------- GEMM ----------------------------------------------------------
// A row stride lda (split-K parts pass pre-offset pointers, K = part size).
// mode 0: fp32 partial (no bias) -> C (z=0) / C2 (z=1)
// mode 1: +bias, GELU -> Ch/Cl ; mode 3: QKV +bias, Q scaled -> Ch/Cl
#define GSTG 3
#define GEMM_SMEM (GSTG*32768 + 1024)

__global__ __launch_bounds__(256, 2)
void gemm_mma(const __nv_bfloat16* __restrict__ Ah, const __nv_bfloat16* __restrict__ Al,
              const __nv_bfloat16* __restrict__ Bh, const __nv_bfloat16* __restrict__ Bl,
              const float* __restrict__ bias,
              float* __restrict__ C, float* __restrict__ C2,
              __nv_bfloat16* __restrict__ Ch, __nv_bfloat16* __restrict__ Cl,
              int M, int N, int K, int lda, int mode)
{
    extern __shared__ char dsm[];
    uint32_t raw = smem_u32(dsm);
    uint32_t s0 = (raw + 1023) & ~1023u;

    int tid = threadIdx.x, wid = tid >> 5, lane = tid & 31;
    int wm = wid & 1, wn = wid >> 1;
    long mBase = (long)blockIdx.y * 128;
    long nBase = (long)blockIdx.x * 128;
    int kOff = blockIdx.z * K;

    float acc[4][4][4];
    #pragma unroll
    for (int i = 0; i < 4; i++)
        #pragma unroll
        for (int j = 0; j < 4; j++)
            #pragma unroll
            for (int q = 0; q < 4; q++) acc[i][j][q] = 0.f;

    int lrow = tid >> 1, lkc0 = (tid & 1) * 2;
    const __nv_bfloat16* Ahp = Ah + (size_t)(mBase + lrow) * lda + kOff;
    const __nv_bfloat16* Alp = Al + (size_t)(mBase + lrow) * lda + kOff;
    const __nv_bfloat16* Bhp = Bh + (size_t)(nBase + lrow) * lda + kOff;
    const __nv_bfloat16* Blp = Bl + (size_t)(nBase + lrow) * lda + kOff;
    uint32_t sw0 = swz(lrow * 64 + lkc0 * 16);
    uint32_t sw1 = swz(lrow * 64 + (lkc0 + 1) * 16);
    const int nIt = K / 32;

    #pragma unroll 1
    for (int pf = 0; pf < 2; pf++) {
        uint32_t sb = s0 + pf * 32768;
        int k0 = pf * 32 + lkc0 * 8;
        cpa16(sb + sw0, Ahp + k0);          cpa16(sb + sw1, Ahp + k0 + 8);
        cpa16(sb + 8192 + sw0, Alp + k0);   cpa16(sb + 8192 + sw1, Alp + k0 + 8);
        cpa16(sb + 16384 + sw0, Bhp + k0);  cpa16(sb + 16384 + sw1, Bhp + k0 + 8);
        cpa16(sb + 24576 + sw0, Blp + k0);  cpa16(sb + 24576 + sw1, Blp + k0 + 8);
        cp_commit();
    }

    #pragma unroll 1
    for (int it = 0; it < nIt; ++it) {
        if (it < nIt - 1) cp_wait<1>(); else cp_wait<0>();
        __syncthreads();
        if (it + 2 < nIt) {
            uint32_t sb = s0 + ((it + 2) % GSTG) * 32768;
            int k0 = (it + 2) * 32 + lkc0 * 8;
            cpa16(sb + sw0, Ahp + k0);          cpa16(sb + sw1, Ahp + k0 + 8);
            cpa16(sb + 8192 + sw0, Alp + k0);   cpa16(sb + 8192 + sw1, Alp + k0 + 8);
            cpa16(sb + 16384 + sw0, Bhp + k0);  cpa16(sb + 16384 + sw1, Bhp + k0 + 8);
            cpa16(sb + 24576 + sw0, Blp + k0);  cpa16(sb + 24576 + sw1, Blp + k0 + 8);
            cp_commit();
        }
        uint32_t base = s0 + (it % GSTG) * 32768;
        #pragma unroll
        for (int ks = 0; ks < 2; ks++) {
            uint32_t kcol = (ks * 2 + (lane >> 4)) * 16;
            int brow = wn * 32 + (lane & 15);
            uint32_t bh[4][2], bl[4][2];
            #pragma unroll
            for (int n2 = 0; n2 < 2; n2++) {
                uint32_t r0, r1, r2, r3;
                ldsm4(r0, r1, r2, r3, base + 16384 + swz((brow + n2 * 16) * 64 + kcol));
                bh[n2*2][0] = r0; bh[n2*2][1] = r2; bh[n2*2+1][0] = r1; bh[n2*2+1][1] = r3;
                ldsm4(r0, r1, r2, r3, base + 24576 + swz((brow + n2 * 16) * 64 + kcol));
                bl[n2*2][0] = r0; bl[n2*2][1] = r2; bl[n2*2+1][0] = r1; bl[n2*2+1][1] = r3;
            }
            int arow = wm * 64 + (lane & 15);
            #pragma unroll
            for (int mt = 0; mt < 4; mt++) {
                uint32_t a[4], al2[4];
                ldsm4(a[0], a[1], a[2], a[3], base + swz((arow + mt * 16) * 64 + kcol));
                ldsm4(al2[0], al2[1], al2[2], al2[3], base + 8192 + swz((arow + mt * 16) * 64 + kcol));
                #pragma unroll
                for (int nt = 0; nt < 4; nt++) mma_bf16(acc[mt][nt], a, bh[nt]);
                #pragma unroll
                for (int nt = 0; nt < 4; nt++) mma_bf16(acc[mt][nt], a, bl[nt]);
                #pragma unroll
                for (int nt = 0; nt < 4; nt++) mma_bf16(acc[mt][nt], al2, bh[nt]);
            }
        }
    }

    float* dst = blockIdx.z ? C2 : C;
    #pragma unroll
    for (int mt = 0; mt < 4; mt++) {
        #pragma unroll
        for (int half = 0; half < 2; half++) {
            long m = mBase + wm * 64 + mt * 16 + (lane >> 2) + half * 8;
            #pragma unroll
            for (int nt = 0; nt < 4; nt++) {
                long n0 = nBase + wn * 32 + nt * 8 + (lane & 3) * 2;
                float v0 = acc[mt][nt][half * 2];
                float v1 = acc[mt][nt][half * 2 + 1];
                if (mode == 0) {
                    *(float2*)(dst + m * N + n0) = make_float2(v0, v1);
                } else {
                    v0 += __ldg(bias + n0); v1 += __ldg(bias + n0 + 1);
                    if (mode == 1) {
                        v0 = 0.5f * v0 * (1.0f + erff(v0 * 0.70710678118654752f));
                        v1 = 0.5f * v1 * (1.0f + erff(v1 * 0.70710678118654752f));
                    } else {
                        float sc = (n0 < DD) ? 0.125f : 1.0f;
                        v0 *= sc; v1 *= sc;
                    }
                    uint32_t ph, pl; pack2(v0, v1, ph, pl);
                    *(uint32_t*)(Ch + m * N + n0) = ph;
                    *(uint32_t*)(Cl + m * N + n0) = pl;
                }
            }
        }
    }
}

// ---------------- flash attention -------------------------------------------------
#define A_QH 0
#define A_QL 16384
#define A_KV 32768
#define A_MK (32768 + 98304)
#define ATTN_SMEM (131072 + 2048 + 1024)

__global__ __launch_bounds__(256, 1)
void attn_flash(const __nv_bfloat16* __restrict__ qkv_h,
                const __nv_bfloat16* __restrict__ qkv_l,
                const int* __restrict__ mask,
                __nv_bfloat16* __restrict__ ctx_h, __nv_bfloat16* __restrict__ ctx_l)
{
    extern __shared__ char dsm[];
    uint32_t raw = smem_u32(dsm);
    uint32_t s0 = (raw + 1023) & ~1023u;
    char* sm = dsm + (s0 - raw);

    int b = blockIdx.z, h = blockIdx.y, qt = blockIdx.x;
    int tid = threadIdx.x, wid = tid >> 5, lane = tid & 31;
    int q0 = b * SS + qt * 128;
    int k0g = b * SS;

    float* maskf = (float*)(sm + A_MK);
    for (int i = tid; i < SS; i += 256) maskf[i] = (float)mask[b * SS + i];

    #pragma unroll
    for (int r2 = 0; r2 < 4; r2++) {
        int i = tid + r2 * 256;
        int row = i >> 3, c = i & 7;
        uint32_t sw = swz(row * 128 + c * 16);
        size_t gq = (size_t)(q0 + row) * NQKV + h * DH + c * 8;
        cpa16(s0 + A_QH + sw, qkv_h + gq);
        cpa16(s0 + A_QL + sw, qkv_l + gq);
    }
    cp_commit();

    auto ldKV = [&](int ch, int stg) {
        uint32_t kb = s0 + A_KV + stg * 32768;
        #pragma unroll
        for (int r2 = 0; r2 < 2; r2++) {
            int i = tid + r2 * 256;
            int row = i >> 3, c = i & 7;
            uint32_t sw = swz(row * 128 + c * 16);
            size_t gk = (size_t)(k0g + ch * 64 + row) * NQKV + DD + h * DH + c * 8;
            cpa16(kb + sw,         qkv_h + gk);
            cpa16(kb + 8192 + sw,  qkv_l + gk);
            cpa16(kb + 16384 + sw, qkv_h + gk + DD);
            cpa16(kb + 24576 + sw, qkv_l + gk + DD);
        }
        cp_commit();
    };
    ldKV(0, 0);
    ldKV(1, 1);

    cp_wait<2>(); __syncthreads();

    uint32_t qh[4][4], ql[4][4];
    {
        int qr = wid * 16 + (lane & 15);
        #pragma unroll
        for (int ks = 0; ks < 4; ks++) {
            uint32_t o2 = swz(qr * 128 + (ks * 2 + (lane >> 4)) * 16);
            ldsm4(qh[ks][0], qh[ks][1], qh[ks][2], qh[ks][3], s0 + A_QH + o2);
            ldsm4(ql[ks][0], ql[ks][1], ql[ks][2], ql[ks][3], s0 + A_QL + o2);
        }
    }

    float M[2] = {-1e30f, -1e30f}, Zs[2] = {0.f, 0.f}, Zm[2] = {0.f, 0.f};
    float o[8][4];
    #pragma unroll
    for (int i = 0; i < 8; i++)
        #pragma unroll
        for (int j = 0; j < 4; j++) o[i][j] = 0.f;

    #pragma unroll 1
    for (int ch = 0; ch < 8; ch++) {
        if (ch < 7) cp_wait<1>(); else cp_wait<0>();
        __syncthreads();
        if (ch + 2 < 8) ldKV(ch + 2, (ch + 2) % 3);

        uint32_t kb = s0 + A_KV + (ch % 3) * 32768;
        float s[8][4];
        #pragma unroll
        for (int i = 0; i < 8; i++)
            #pragma unroll
            for (int j = 0; j < 4; j++) s[i][j] = 0.f;

        #pragma unroll
        for (int n4 = 0; n4 < 4; n4++) {
            int br = n4 * 16 + (lane & 15);
            #pragma unroll
            for (int ks = 0; ks < 4; ks++) {
                uint32_t kcol = (ks * 2 + (lane >> 4)) * 16;
                uint32_t r0, r1, r2, r3;
                uint32_t bh0[2], bh1[2], bl0[2], bl1[2];
                ldsm4(r0, r1, r2, r3, kb + swz(br * 128 + kcol));
                bh0[0] = r0; bh0[1] = r2; bh1[0] = r1; bh1[1] = r3;
                ldsm4(r0, r1, r2, r3, kb + 8192 + swz(br * 128 + kcol));
                bl0[0] = r0; bl0[1] = r2; bl1[0] = r1; bl1[1] = r3;
                mma_bf16(s[n4*2], qh[ks], bh0);  mma_bf16(s[n4*2+1], qh[ks], bh1);
                mma_bf16(s[n4*2], qh[ks], bl0);  mma_bf16(s[n4*2+1], qh[ks], bl1);
                mma_bf16(s[n4*2], ql[ks], bh0);  mma_bf16(s[n4*2+1], ql[ks], bh1);
            }
        }

        #pragma unroll
        for (int g = 0; g < 2; g++) {
            float mx = -1e30f;
            #pragma unroll
            for (int nt = 0; nt < 8; nt++)
                mx = fmaxf(mx, fmaxf(s[nt][2*g], s[nt][2*g+1]));
            mx = fmaxf(mx, __shfl_xor_sync(0xffffffffu, mx, 1));
            mx = fmaxf(mx, __shfl_xor_sync(0xffffffffu, mx, 2));
            float Mn = fmaxf(M[g], mx);
            float fac = __expf(M[g] - Mn);
            float zc = 0.f, zmc = 0.f;
            #pragma unroll
            for (int nt = 0; nt < 8; nt++) {
                #pragma unroll
                for (int e = 0; e < 2; e++) {
                    int col = ch * 64 + nt * 8 + (lane & 3) * 2 + e;
                    float ex = __expf(s[nt][2*g+e] - Mn);
                    float mm = maskf[col];
                    zc += ex; zmc += ex * mm;
                    s[nt][2*g+e] = ex * mm;
                }
            }
            zc += __shfl_xor_sync(0xffffffffu, zc, 1);
            zc += __shfl_xor_sync(0xffffffffu, zc, 2);
            zmc += __shfl_xor_sync(0xffffffffu, zmc, 1);
            zmc += __shfl_xor_sync(0xffffffffu, zmc, 2);
            Zs[g] = Zs[g] * fac + zc;
            Zm[g] = Zm[g] * fac + zmc;
            M[g] = Mn;
            #pragma unroll
            for (int nt = 0; nt < 8; nt++) { o[nt][2*g] *= fac; o[nt][2*g+1] *= fac; }
        }

        uint32_t ah[4][4], al[4][4];
        #pragma unroll
        for (int kt = 0; kt < 4; kt++) {
            pack2(s[2*kt][0],   s[2*kt][1],   ah[kt][0], al[kt][0]);
            pack2(s[2*kt][2],   s[2*kt][3],   ah[kt][1], al[kt][1]);
            pack2(s[2*kt+1][0], s[2*kt+1][1], ah[kt][2], al[kt][2]);
            pack2(s[2*kt+1][2], s[2*kt+1][3], ah[kt][3], al[kt][3]);
        }

        uint32_t vb = kb + 16384;
        #pragma unroll
        for (int n4 = 0; n4 < 4; n4++) {
            #pragma unroll
            for (int kt = 0; kt < 4; kt++) {
                uint32_t addr = swz((kt * 16 + (lane & 15)) * 128 + n4 * 32 + (lane >> 4) * 16);
                uint32_t r0, r1, r2, r3;
                uint32_t bh0[2], bh1[2], bl0[2], bl1[2];
                ldsm4t(r0, r1, r2, r3, vb + addr);
                bh0[0] = r0; bh0[1] = r1; bh1[0] = r2; bh1[1] = r3;
                ldsm4t(r0, r1, r2, r3, vb + 8192 + addr);
                bl0[0] = r0; bl0[1] = r1; bl1[0] = r2; bl1[1] = r3;
                mma_bf16(o[n4*2], ah[kt], bh0);  mma_bf16(o[n4*2+1], ah[kt], bh1);
                mma_bf16(o[n4*2], ah[kt], bl0);  mma_bf16(o[n4*2+1], ah[kt], bl1);
                mma_bf16(o[n4*2], al[kt], bh0);  mma_bf16(o[n4*2+1], al[kt], bh1);
            }
        }
    }

    #pragma unroll
    for (int g = 0; g < 2; g++) {
        float den = fmaxf(Zm[g], 1e-9f * Zs[g]);
        float rcp = 1.0f / den;
        size_t row = q0 + wid * 16 + (lane >> 2) + g * 8;
        #pragma unroll
        for (int nt = 0; nt < 8; nt++) {
            int col = h * DH + nt * 8 + (lane & 3) * 2;
            uint32_t ph, pl;
            pack2(o[nt][2*g] * rcp, o[nt][2*g+1] * rcp, ph, pl);
            *(uint32_t*)(ctx_h + row * DD + col) = ph;
            *(uint32_t*)(ctx_l + row * DD + col) = pl;
        }
    }
}

// ---------------- pool + normalize ------------------------------------------------
__global__ void pool_kernel(const float* __restrict__ h, const int* __restrict__ mask,
                            float* __restrict__ out)
{
    __shared__ float sent[DD];
    __shared__ float red[32];
    int b = blockIdx.x, tid = threadIdx.x;
    float ms = 0.f;
    for (int s = tid; s < SS; s += 256) ms += (float)mask[b * SS + s];
    ms = blockReduceSum(ms, red);
    float inv = 1.0f / fmaxf(ms, 1e-6f);
    for (int d = tid; d < DD; d += 256) {
        float a = 0.f;
        const float* hp = h + ((size_t)b * SS) * DD + d;
        const int* mp = mask + b * SS;
        for (int s = 0; s < SS; s++) a += hp[(size_t)s * DD] * (float)mp[s];
        sent[d] = a * inv;
    }
    __syncthreads();
    float sq = 0.f;
    for (int d = tid; d < DD; d += 256) sq += sent[d] * sent[d];
    sq = blockReduceSum(sq, red);
    float rn = 1.0f / fmaxf(sqrtf(sq), 1e-12f);
    for (int d = tid; d < DD; d += 256) out[b * DD + d] = sent[d] * rn;
}

// ---------------- launch -----------------------------------------------------------
extern "C" void kernel_launch(void* const* d_in, const int* in_sizes, int n_in,
                              void* d_out, int out_size)
{
    const int*   input_ids = (const int*)  d_in[0];
    const int*   amask     = (const int*)  d_in[1];
    const float* word_emb  = (const float*)d_in[2];
    const float* pos_emb   = (const float*)d_in[3];
    const float* type_emb  = (const float*)d_in[4];
    const float* emb_g     = (const float*)d_in[5];
    const float* emb_b     = (const float*)d_in[6];
    const float* Wq = (const float*)d_in[7];  const float* bq = (const float*)d_in[8];
    const float* Wk = (const float*)d_in[9];  const float* bk = (const float*)d_in[10];
    const float* Wv = (const float*)d_in[11]; const float* bv = (const float*)d_in[12];
    const float* Wo = (const float*)d_in[13]; const float* bo = (const float*)d_in[14];
    const float* ln1g = (const float*)d_in[15]; const float* ln1b = (const float*)d_in[16];
    const float* Wi = (const float*)d_in[17]; const float* bi = (const float*)d_in[18];
    const float* Wf = (const float*)d_in[19]; const float* bf = (const float*)d_in[20];
    const float* ln2g = (const float*)d_in[21]; const float* ln2b = (const float*)d_in[22];
    float* out = (float*)d_out;

    float *p_h, *p_t1, *p_t2, *p_bqkv;
    __nv_bfloat16 *p_hh, *p_hl, *p_qh, *p_ql, *p_ch, *p_cl, *p_fh, *p_fl;
    __nv_bfloat16 *wqkv_h, *wqkv_l, *wo_h, *wo_l, *wi_h, *wi_l, *wf_h, *wf_l;
    cudaGetSymbolAddress((void**)&p_h,  g_h);
    cudaGetSymbolAddress((void**)&p_t1, g_t1);
    cudaGetSymbolAddress((void**)&p_t2, g_t2);
    cudaGetSymbolAddress((void**)&p_bqkv, g_bqkv);
    cudaGetSymbolAddress((void**)&p_hh, g_h_hi);
    cudaGetSymbolAddress((void**)&p_hl, g_h_lo);
    cudaGetSymbolAddress((void**)&p_qh, g_qkv_h);
    cudaGetSymbolAddress((void**)&p_ql, g_qkv_l);
    cudaGetSymbolAddress((void**)&p_ch, g_ctx_hi);
    cudaGetSymbolAddress((void**)&p_cl, g_ctx_lo);
    cudaGetSymbolAddress((void**)&p_fh, g_ff_hi);
    cudaGetSymbolAddress((void**)&p_fl, g_ff_lo);
    cudaGetSymbolAddress((void**)&wqkv_h, g_Wqkv_h); cudaGetSymbolAddress((void**)&wqkv_l, g_Wqkv_l);
    cudaGetSymbolAddress((void**)&wo_h, g_WoT_h);    cudaGetSymbolAddress((void**)&wo_l, g_WoT_l);
    cudaGetSymbolAddress((void**)&wi_h, g_WiT_h);    cudaGetSymbolAddress((void**)&wi_l, g_WiT_l);
    cudaGetSymbolAddress((void**)&wf_h, g_WfT_h);    cudaGetSymbolAddress((void**)&wf_l, g_WfT_l);

    cudaFuncSetAttribute(gemm_mma, cudaFuncAttributeMaxDynamicSharedMemorySize, GEMM_SMEM);
    cudaFuncSetAttribute(attn_flash, cudaFuncAttributeMaxDynamicSharedMemorySize, ATTN_SMEM);

    trans_all<<<LL * 6912, dim3(32, 8)>>>(Wq, Wk, Wv, Wo, Wi, Wf);
    fuse_bias<<<(LL * NQKV + 255) / 256, 256>>>(bq, bk, bv);
    embed_ln_kernel<<<MTOK, 256>>>(input_ids, word_emb, pos_emb, type_emb,
                                   emb_g, emb_b, p_h, p_hh, p_hl);

    dim3 gQKV(NQKV / 128, MTOK / 128, 1);
    dim3 gSK (DD   / 128, MTOK / 128, 2);   // split-K grids for Wo / Wf
    dim3 gFF (FFD  / 128, MTOK / 128, 1);

    for (int l = 0; l < LL; l++) {
        size_t wdd = (size_t)l * DD * DD;
        size_t wdf = (size_t)l * DD * FFD;
        size_t wqk = (size_t)l * NQKV * DD;

        gemm_mma<<<gQKV, 256, GEMM_SMEM>>>(p_hh, p_hl, wqkv_h + wqk, wqkv_l + wqk,
                                           p_bqkv + l * NQKV, nullptr, nullptr,
                                           p_qh, p_ql, MTOK, NQKV, DD, DD, 3);

        attn_flash<<<dim3(4, HH, BB), 256, ATTN_SMEM>>>(p_qh, p_ql, amask, p_ch, p_cl);

        // Wo: split-K=2 (K=384 per part)
        gemm_mma<<<gSK, 256, GEMM_SMEM>>>(p_ch, p_cl, wo_h + wdd, wo_l + wdd,
                                          nullptr, p_t1, p_t2, nullptr, nullptr,
                                          MTOK, DD, DD / 2, DD, 0);
        ln_sum_kernel<<<MTOK, 256>>>(p_t1, p_t2, bo + l * DD, p_h,
                                     ln1g + l * DD, ln1b + l * DD, p_h, p_hh, p_hl);

        gemm_mma<<<gFF, 256, GEMM_SMEM>>>(p_hh, p_hl, wi_h + wdf, wi_l + wdf,
                                          bi + l * FFD, nullptr, nullptr, p_fh, p_fl,
                                          MTOK, FFD, DD, DD, 1);

        // Wf: split-K=2 (K=1536 per part)
        gemm_mma<<<gSK, 256, GEMM_SMEM>>>(p_fh, p_fl, wf_h + wdf, wf_l + wdf,
                                          nullptr, p_t1, p_t2, nullptr, nullptr,
                                          MTOK, DD, FFD / 2, FFD, 0);
        ln_sum_kernel<<<MTOK, 256>>>(p_t1, p_t2, bf + l * DD, p_h,
                                     ln2g + l * DD, ln2b + l * DD, p_h, p_hh, p_hl);
    }

    pool_kernel<<<BB, 256>>>(p_h, amask, out);
}